// round 8
// baseline (speedup 1.0000x reference)
#include <cuda_runtime.h>
#include <cuda_bf16.h>
#include <cstdint>

#define NS 4
// smem (bytes): T = float[64][257], 2 chunk bufs, path scratch
#define SB_BUF  65792
#define SB_PLOG 102656             // float[9*64]
#define SB_PB   104960             // float[4*64]
#define SMEM_BYTES 105984          // 2 CTAs/SM

__device__ __align__(256) __nv_bfloat16 g_kdh[256*256*72];
__device__ __align__(256) __nv_bfloat16 g_kdl[256*256*72];
__device__ __align__(256) __nv_bfloat16 g_vh [256*256*72];
__device__ __align__(256) __nv_bfloat16 g_vl [256*256*72];
__device__ __align__(256) __nv_bfloat16 g_qh [2048*72];
__device__ __align__(256) __nv_bfloat16 g_ql [2048*72];
__device__ float g_kpath[255*64];

__device__ __forceinline__ uint32_t cvta(const void* p){
    uint32_t a; asm("{.reg .u64 t; cvta.to.shared.u64 t,%1; cvt.u32.u64 %0,t;}":"=r"(a):"l"(p)); return a;
}
__device__ __forceinline__ void ldsm2(uint32_t r[2], uint32_t a){
    asm volatile("ldmatrix.sync.aligned.m8n8.x2.shared.b16 {%0,%1},[%2];"
        :"=r"(r[0]),"=r"(r[1]):"r"(a));
}
__device__ __forceinline__ void ldsm2t(uint32_t r[2], uint32_t a){
    asm volatile("ldmatrix.sync.aligned.m8n8.x2.trans.shared.b16 {%0,%1},[%2];"
        :"=r"(r[0]),"=r"(r[1]):"r"(a));
}
__device__ __forceinline__ void mma(float c[4], const uint32_t a[4], const uint32_t b[2]){
    asm volatile("mma.sync.aligned.m16n8k16.row.col.f32.bf16.bf16.f32 "
        "{%0,%1,%2,%3},{%4,%5,%6,%7},{%8,%9},{%0,%1,%2,%3};"
        :"+f"(c[0]),"+f"(c[1]),"+f"(c[2]),"+f"(c[3])
        :"r"(a[0]),"r"(a[1]),"r"(a[2]),"r"(a[3]),"r"(b[0]),"r"(b[1]));
}
__device__ __forceinline__ uint32_t prmt(uint32_t a, uint32_t b, uint32_t s){
    uint32_t r; asm("prmt.b32 %0,%1,%2,%3;":"=r"(r):"r"(a),"r"(b),"r"(s)); return r;
}
__device__ __forceinline__ void cp16(uint32_t d, const void* s){
    asm volatile("cp.async.cg.shared.global [%0],[%1],16;"::"r"(d),"l"(s));
}
#define CP_COMMIT() asm volatile("cp.async.commit_group;":::"memory")
#define CP_WAIT(N)  asm volatile("cp.async.wait_group %0;"::"n"(N):"memory")
__device__ __forceinline__ void split2(float x, __nv_bfloat16& h, __nv_bfloat16& lo){
    h = __float2bfloat16(x); lo = __float2bfloat16(x - __bfloat162float(h));
}
__device__ __forceinline__ uint32_t packsplit(float x){
    __nv_bfloat16 h, lo; split2(x, h, lo);
    return (uint32_t)__bfloat16_as_ushort(h) | ((uint32_t)__bfloat16_as_ushort(lo) << 16);
}
__device__ __forceinline__ float fast_sigmoid(float x){
    float e; asm("ex2.approx.f32 %0,%1;":"=f"(e):"f"(-x*1.4426950408889634f));
    float r; asm("rcp.approx.f32 %0,%1;":"=f"(r):"f"(1.f+e));
    return r;
}

// ----------------------------- prep kernels -----------------------------
__global__ void prep_kd(const float* __restrict__ tk){
    int bx = blockIdx.x, s = bx >> 8, r = bx & 255, k = threadIdx.x;
    float d = 0.f;
    if (r < 255 && k < 64){
        int rp = r+1, e = 31-__clz(rp), pj = rp-(1<<e);
        int j = e ? (int)(__brev((unsigned)pj) >> (32-e)) : 0;
        size_t node = (((size_t)1<<(e+8))-1) + (size_t)s*(1<<e) + j;
        d = tk[node*128 + k] - tk[node*128 + 64 + k];
    }
    __nv_bfloat16 h, lo; split2(d, h, lo);
    g_kdh[(size_t)bx*72 + k] = h; g_kdl[(size_t)bx*72 + k] = lo;
}
__global__ void prep_v(const float* __restrict__ tv){
    int bx = blockIdx.x, s = bx >> 8, r = bx & 255, k = threadIdx.x;
    size_t leaf = (size_t)s*256 + (__brev((unsigned)r) >> 24);
    float v = (k < 64) ? tv[leaf*64 + k] : 0.f;
    __nv_bfloat16 h, lo; split2(v, h, lo);
    g_vh[(size_t)bx*72 + k] = h; g_vl[(size_t)bx*72 + k] = lo;
}
__global__ void prep_q(const float* __restrict__ q){
    int b = blockIdx.x, k = threadIdx.x;
    float v = (k < 64) ? q[b*64 + k] : 0.f;
    __nv_bfloat16 h, lo; split2(v, h, lo);
    g_qh[b*72 + k] = h; g_ql[b*72 + k] = lo;
}
__global__ void prep_kpath(const float* __restrict__ tk){
    int n = blockIdx.x, k = threadIdx.x;
    g_kpath[n*64 + k] = tk[n*128 + k] - tk[n*128 + 64 + k];
}

// ----------------------------- main kernel -----------------------------
__global__ __launch_bounds__(256, 2)
void tree_kernel(const float* __restrict__ q32, float* __restrict__ out)
{
    extern __shared__ char smc[];
    float* fT = (float*)smc;
    uint32_t* uT = (uint32_t*)smc;
    float* fPL = (float*)(smc + SB_PLOG);
    float* fPB = (float*)(smc + SB_PB);
    const uint32_t SB = cvta(smc);
    const int tid = threadIdx.x, w = tid >> 5, l = tid & 31;
    const int btile = blockIdx.x, sg = blockIdx.y;
    const int b_base = btile * 64;
    const int bt = w & 3, grp = w >> 2;
    const int total = NS * 8;

    auto issue = [&](int t){
        if (t >= total) return;
        int c = t & 7, si = t >> 3;
        size_t off = ((size_t)(sg*NS + si)*256 + (size_t)(c & 3)*64)*72;
        const __nv_bfloat16 *ph = (c < 4) ? g_kdh + off : g_vh + off;
        const __nv_bfloat16 *pl = (c < 4) ? g_kdl + off : g_vl + off;
        uint32_t dst = SB + SB_BUF + (uint32_t)(t & 1)*18432;
        for (int i = tid; i < 576; i += 256){
            cp16(dst + i*16,        (const char*)ph + i*16);
            cp16(dst + 9216 + i*16, (const char*)pl + i*16);
        }
        CP_COMMIT();
    };

    issue(0); issue(1);

    // ---- Q fragments -> registers ----
    uint32_t QAh[4][4], QAl[4][4];
    {
        int r0 = b_base + bt*16 + (l >> 2);
        int c0 = 2 * (l & 3);
        #pragma unroll
        for (int kt = 0; kt < 4; kt++){
            int k0 = kt*16 + c0;
            QAh[kt][0] = *(const uint32_t*)&g_qh[(size_t)r0*72 + k0];
            QAh[kt][1] = *(const uint32_t*)&g_qh[(size_t)(r0+8)*72 + k0];
            QAh[kt][2] = *(const uint32_t*)&g_qh[(size_t)r0*72 + k0 + 8];
            QAh[kt][3] = *(const uint32_t*)&g_qh[(size_t)(r0+8)*72 + k0 + 8];
            QAl[kt][0] = *(const uint32_t*)&g_ql[(size_t)r0*72 + k0];
            QAl[kt][1] = *(const uint32_t*)&g_ql[(size_t)(r0+8)*72 + k0];
            QAl[kt][2] = *(const uint32_t*)&g_ql[(size_t)r0*72 + k0 + 8];
            QAl[kt][3] = *(const uint32_t*)&g_ql[(size_t)(r0+8)*72 + k0 + 8];
        }
    }

    // ---- fused phase-1: 9 path logits per batch (fp32), then base probs ----
    for (int i = tid; i < 9*64; i += 256){
        int n = i >> 6, b = i & 63;
        int node = (n < 7) ? ((1 << n) - 1 + (sg >> (6 - n)))
                           : (127 + 2*sg + (n - 7));
        const float* qr = q32 + (size_t)(b_base + b)*64;
        const float* kp = g_kpath + node*64;
        float acc = 0.f;
        #pragma unroll 16
        for (int k = 0; k < 64; k++) acc = fmaf(qr[k], kp[k], acc);
        fPL[n*64 + b] = acc;
    }
    __syncthreads();
    if (tid < 64){
        int b = tid;
        float common = 1.f;
        #pragma unroll
        for (int e = 0; e < 6; e++){
            int bit = (sg >> (5 - e)) & 1;
            float x = fPL[e*64 + b];
            common *= fast_sigmoid(bit ? -x : x);
        }
        float s6  = fast_sigmoid(fPL[6*64 + b]);
        float s7a = fast_sigmoid(fPL[7*64 + b]);
        float s7b = fast_sigmoid(fPL[8*64 + b]);
        fPB[0*64 + b] = common * s6 * s7a;
        fPB[1*64 + b] = common * s6 * (1.f - s7a);
        fPB[2*64 + b] = common * (1.f - s6) * s7b;
        fPB[3*64 + b] = common * (1.f - s6) * (1.f - s7b);
    }

    float acc2[4][4];
    #pragma unroll
    for (int i = 0; i < 4; i++)
        #pragma unroll
        for (int j = 0; j < 4; j++) acc2[i][j] = 0.f;

    for (int si = 0; si < NS; si++){
        // ---------------- GEMM1: 4 passes of 64 n-columns ----------------
        for (int p = 0; p < 4; p++){
            int t = si*8 + p;
            if (t + 1 < total) CP_WAIT(1); else CP_WAIT(0);
            __syncthreads();
            uint32_t kb = SB + SB_BUF + (uint32_t)(t & 1)*18432;
            float a1[4][4];
            #pragma unroll
            for (int i = 0; i < 4; i++)
                #pragma unroll
                for (int j = 0; j < 4; j++) a1[i][j] = 0.f;
            #pragma unroll
            for (int kt = 0; kt < 4; kt++){
                #pragma unroll
                for (int nt = 0; nt < 4; nt++){
                    uint32_t bo = kb +
                        (uint32_t)(((grp*32 + nt*8 + (l & 7))*72 + kt*16 + (((l >> 3) & 1) << 3)) << 1);
                    uint32_t Bh[2], Bl[2]; ldsm2(Bh, bo); ldsm2(Bl, bo + 9216);
                    mma(a1[nt], QAh[kt], Bh); mma(a1[nt], QAh[kt], Bl); mma(a1[nt], QAl[kt], Bh);
                }
            }
            #pragma unroll
            for (int nt = 0; nt < 4; nt++){
                int r = bt*16 + (l >> 2);
                int cc = p*64 + grp*32 + nt*8 + 2*(l & 3);
                fT[r*257 + 1 + cc]     = a1[nt][0];
                fT[r*257 + 2 + cc]     = a1[nt][1];
                fT[(r+8)*257 + 1 + cc] = a1[nt][2];
                fT[(r+8)*257 + 2 + cc] = a1[nt][3];
            }
            __syncthreads();
            if (t + 2 < total) issue(t + 2);
        }
        if (tid < 64) fT[tid*257] = fPB[si*64 + tid];
        __syncthreads();

        // ---------------- expansion (warp-private 8 batches) ----------------
        {
            const int wb = w * 8;
            #pragma unroll
            for (int e = 0; e < 7; e++){
                int half = 1 << e;
                for (int it = l; it < 8*half; it += 32){
                    int b = wb + (it & 7), pos = it >> 3;
                    float sg0 = fast_sigmoid(fT[b*257 + half + pos]);
                    float v = fT[b*257 + pos];
                    float c0 = v * sg0;
                    fT[b*257 + pos]        = c0;
                    fT[b*257 + pos + half] = v - c0;
                }
                __syncwarp();
            }
            for (int it = l; it < 1024; it += 32){   // level 7 -> packed split
                int b = wb + (it & 7), pos = it >> 3;
                float sg0 = fast_sigmoid(fT[b*257 + 128 + pos]);
                float v = fT[b*257 + pos];
                float c0 = v * sg0, c1 = v - c0;
                uT[b*257 + pos]       = packsplit(c0);
                uT[b*257 + pos + 128] = packsplit(c1);
            }
        }
        __syncthreads();

        // ---------------- GEMM2: 4 k-chunks, register accumulator ----------------
        for (int c = 0; c < 4; c++){
            int t = si*8 + 4 + c;
            if (t + 1 < total) CP_WAIT(1); else CP_WAIT(0);
            __syncthreads();
            uint32_t vb = SB + SB_BUF + (uint32_t)(t & 1)*18432;
            #pragma unroll
            for (int kt = 0; kt < 4; kt++){
                int r0 = bt*16 + (l >> 2);
                int kk = c*64 + kt*16 + 2*(l & 3);
                uint32_t Ah[4], Al[4];
                {
                    uint32_t p0 = uT[r0*257 + kk],       p1 = uT[r0*257 + kk + 1];
                    Ah[0] = prmt(p0, p1, 0x5410); Al[0] = prmt(p0, p1, 0x7632);
                    p0 = uT[(r0+8)*257 + kk];     p1 = uT[(r0+8)*257 + kk + 1];
                    Ah[1] = prmt(p0, p1, 0x5410); Al[1] = prmt(p0, p1, 0x7632);
                    p0 = uT[r0*257 + kk + 8];     p1 = uT[r0*257 + kk + 9];
                    Ah[2] = prmt(p0, p1, 0x5410); Al[2] = prmt(p0, p1, 0x7632);
                    p0 = uT[(r0+8)*257 + kk + 8]; p1 = uT[(r0+8)*257 + kk + 9];
                    Ah[3] = prmt(p0, p1, 0x5410); Al[3] = prmt(p0, p1, 0x7632);
                }
                #pragma unroll
                for (int dt = 0; dt < 4; dt++){
                    uint32_t bo = vb +
                        (uint32_t)(((kt*16 + (l & 15))*72 + grp*32 + dt*8) << 1);
                    uint32_t Bh[2], Bl[2]; ldsm2t(Bh, bo); ldsm2t(Bl, bo + 9216);
                    mma(acc2[dt], Ah, Bh); mma(acc2[dt], Ah, Bl); mma(acc2[dt], Al, Bh);
                }
            }
            __syncthreads();
            if (t + 2 < total) issue(t + 2);
        }
    }

    // ---------------- epilogue: one atomic pass per CTA ----------------
    #pragma unroll
    for (int dt = 0; dt < 4; dt++){
        int r = b_base + bt*16 + (l >> 2);
        int cc = grp*32 + dt*8 + 2*(l & 3);
        atomicAdd(&out[(size_t)r*64 + cc],         acc2[dt][0]);
        atomicAdd(&out[(size_t)r*64 + cc + 1],     acc2[dt][1]);
        atomicAdd(&out[(size_t)(r+8)*64 + cc],     acc2[dt][2]);
        atomicAdd(&out[(size_t)(r+8)*64 + cc + 1], acc2[dt][3]);
    }
}

extern "C" void kernel_launch(void* const* d_in, const int* in_sizes, int n_in,
                              void* d_out, int out_size) {
    const float* q  = (const float*)d_in[0];
    const float* tk = (const float*)d_in[1];
    const float* tv = (const float*)d_in[2];
    float* out = (float*)d_out;

    cudaFuncSetAttribute(tree_kernel,
                         cudaFuncAttributeMaxDynamicSharedMemorySize, SMEM_BYTES);

    prep_kd<<<65536, 72>>>(tk);
    prep_v<<<65536, 72>>>(tv);
    prep_q<<<2048, 72>>>(q);
    prep_kpath<<<255, 64>>>(tk);
    cudaMemsetAsync(out, 0, (size_t)2048 * 64 * sizeof(float));
    tree_kernel<<<dim3(32, 64), 256, SMEM_BYTES>>>(q, out);
}

// round 9
// speedup vs baseline: 1.3170x; 1.3170x over previous
#include <cuda_runtime.h>
#include <cuda_bf16.h>
#include <cstdint>

#define NS 4
// smem (bytes): T = float[64][257], 2 chunk bufs, path scratch
#define SB_BUF  65792
#define SB_PLOG 102656             // float[9*64]
#define SB_PB   104960             // float[4*64]
#define SMEM_BYTES 105984          // 2 CTAs/SM

__device__ __align__(256) __nv_bfloat16 g_kdh[256*256*72];
__device__ __align__(256) __nv_bfloat16 g_kdl[256*256*72];
__device__ __align__(256) __nv_bfloat16 g_vh [256*256*72];
__device__ __align__(256) __nv_bfloat16 g_vl [256*256*72];
__device__ __align__(256) __nv_bfloat16 g_qh [2048*72];
__device__ __align__(256) __nv_bfloat16 g_ql [2048*72];
__device__ float g_plog[255*2048];  // fp32 logits for top-255 nodes

__device__ __forceinline__ uint32_t cvta(const void* p){
    uint32_t a; asm("{.reg .u64 t; cvta.to.shared.u64 t,%1; cvt.u32.u64 %0,t;}":"=r"(a):"l"(p)); return a;
}
__device__ __forceinline__ void ldsm2(uint32_t r[2], uint32_t a){
    asm volatile("ldmatrix.sync.aligned.m8n8.x2.shared.b16 {%0,%1},[%2];"
        :"=r"(r[0]),"=r"(r[1]):"r"(a));
}
__device__ __forceinline__ void ldsm2t(uint32_t r[2], uint32_t a){
    asm volatile("ldmatrix.sync.aligned.m8n8.x2.trans.shared.b16 {%0,%1},[%2];"
        :"=r"(r[0]),"=r"(r[1]):"r"(a));
}
__device__ __forceinline__ void mma(float c[4], const uint32_t a[4], const uint32_t b[2]){
    asm volatile("mma.sync.aligned.m16n8k16.row.col.f32.bf16.bf16.f32 "
        "{%0,%1,%2,%3},{%4,%5,%6,%7},{%8,%9},{%0,%1,%2,%3};"
        :"+f"(c[0]),"+f"(c[1]),"+f"(c[2]),"+f"(c[3])
        :"r"(a[0]),"r"(a[1]),"r"(a[2]),"r"(a[3]),"r"(b[0]),"r"(b[1]));
}
__device__ __forceinline__ uint32_t prmt(uint32_t a, uint32_t b, uint32_t s){
    uint32_t r; asm("prmt.b32 %0,%1,%2,%3;":"=r"(r):"r"(a),"r"(b),"r"(s)); return r;
}
__device__ __forceinline__ void cp16(uint32_t d, const void* s){
    asm volatile("cp.async.cg.shared.global [%0],[%1],16;"::"r"(d),"l"(s));
}
#define CP_COMMIT() asm volatile("cp.async.commit_group;":::"memory")
#define CP_WAIT(N)  asm volatile("cp.async.wait_group %0;"::"n"(N):"memory")
__device__ __forceinline__ void split2(float x, __nv_bfloat16& h, __nv_bfloat16& lo){
    h = __float2bfloat16(x); lo = __float2bfloat16(x - __bfloat162float(h));
}
__device__ __forceinline__ uint32_t packsplit(float x){
    __nv_bfloat16 h, lo; split2(x, h, lo);
    return (uint32_t)__bfloat16_as_ushort(h) | ((uint32_t)__bfloat16_as_ushort(lo) << 16);
}
__device__ __forceinline__ float fast_sigmoid(float x){
    float e; asm("ex2.approx.f32 %0,%1;":"=f"(e):"f"(-x*1.4426950408889634f));
    float r; asm("rcp.approx.f32 %0,%1;":"=f"(r):"f"(1.f+e));
    return r;
}

// ----------------------------- prep kernels -----------------------------
__global__ void prep_kd(const float* __restrict__ tk){
    int bx = blockIdx.x, s = bx >> 8, r = bx & 255, k = threadIdx.x;
    float d = 0.f;
    if (r < 255 && k < 64){
        int rp = r+1, e = 31-__clz(rp), pj = rp-(1<<e);
        int j = e ? (int)(__brev((unsigned)pj) >> (32-e)) : 0;
        size_t node = (((size_t)1<<(e+8))-1) + (size_t)s*(1<<e) + j;
        d = tk[node*128 + k] - tk[node*128 + 64 + k];
    }
    __nv_bfloat16 h, lo; split2(d, h, lo);
    g_kdh[(size_t)bx*72 + k] = h; g_kdl[(size_t)bx*72 + k] = lo;
}
__global__ void prep_v(const float* __restrict__ tv){
    int bx = blockIdx.x, s = bx >> 8, r = bx & 255, k = threadIdx.x;
    size_t leaf = (size_t)s*256 + (__brev((unsigned)r) >> 24);
    float v = (k < 64) ? tv[leaf*64 + k] : 0.f;
    __nv_bfloat16 h, lo; split2(v, h, lo);
    g_vh[(size_t)bx*72 + k] = h; g_vl[(size_t)bx*72 + k] = lo;
}
__global__ void prep_q(const float* __restrict__ q){
    int b = blockIdx.x, k = threadIdx.x;
    float v = (k < 64) ? q[b*64 + k] : 0.f;
    __nv_bfloat16 h, lo; split2(v, h, lo);
    g_qh[b*72 + k] = h; g_ql[b*72 + k] = lo;
}

// Path logits for top-255 nodes: L[n][b] = q[b] . (k0[n]-k1[n]), fp32, coalesced.
// smem: qs[64][65] (transposed) + kp[255][64]
#define PLOG_SMEM ((64*65 + 255*64) * 4)
__global__ void prep_plog(const float* __restrict__ q, const float* __restrict__ tk){
    extern __shared__ float ps[];
    float* qs = ps;                 // [k][b] stride 65
    float* kp = ps + 64*65;         // [n][k] stride 64
    const int tid = threadIdx.x;
    const int b_base = blockIdx.x * 64;
    for (int i = tid; i < 64*64; i += 256){
        int b = i >> 6, k = i & 63;
        qs[k*65 + b] = q[(size_t)(b_base + b)*64 + k];
    }
    for (int i = tid; i < 255*64; i += 256){
        int n = i >> 6, k = i & 63;
        kp[i] = tk[(size_t)n*128 + k] - tk[(size_t)n*128 + 64 + k];
    }
    __syncthreads();
    const int b = tid & 63, ng = tid >> 6;   // 4 node groups
    for (int j = 0; j < 64; j++){
        int n = ng*64 + j;
        if (n >= 255) break;
        float acc = 0.f;
        #pragma unroll 16
        for (int k = 0; k < 64; k++)
            acc = fmaf(qs[k*65 + b], kp[n*64 + k], acc);
        g_plog[(size_t)n*2048 + b_base + b] = acc;
    }
}

// ----------------------------- main kernel -----------------------------
__global__ __launch_bounds__(256, 2)
void tree_kernel(float* __restrict__ out)
{
    extern __shared__ char smc[];
    float* fT = (float*)smc;
    uint32_t* uT = (uint32_t*)smc;
    float* fPL = (float*)(smc + SB_PLOG);
    float* fPB = (float*)(smc + SB_PB);
    const uint32_t SB = cvta(smc);
    const int tid = threadIdx.x, w = tid >> 5, l = tid & 31;
    const int btile = blockIdx.x, sg = blockIdx.y;
    const int b_base = btile * 64;
    const int bt = w & 3, grp = w >> 2;
    const int total = NS * 8;

    auto issue = [&](int t){
        if (t >= total) return;
        int c = t & 7, si = t >> 3;
        size_t off = ((size_t)(sg*NS + si)*256 + (size_t)(c & 3)*64)*72;
        const __nv_bfloat16 *ph = (c < 4) ? g_kdh + off : g_vh + off;
        const __nv_bfloat16 *pl = (c < 4) ? g_kdl + off : g_vl + off;
        uint32_t dst = SB + SB_BUF + (uint32_t)(t & 1)*18432;
        for (int i = tid; i < 576; i += 256){
            cp16(dst + i*16,        (const char*)ph + i*16);
            cp16(dst + 9216 + i*16, (const char*)pl + i*16);
        }
        CP_COMMIT();
    };

    issue(0); issue(1);

    // ---- Q fragments -> registers ----
    uint32_t QAh[4][4], QAl[4][4];
    {
        int r0 = b_base + bt*16 + (l >> 2);
        int c0 = 2 * (l & 3);
        #pragma unroll
        for (int kt = 0; kt < 4; kt++){
            int k0 = kt*16 + c0;
            QAh[kt][0] = *(const uint32_t*)&g_qh[(size_t)r0*72 + k0];
            QAh[kt][1] = *(const uint32_t*)&g_qh[(size_t)(r0+8)*72 + k0];
            QAh[kt][2] = *(const uint32_t*)&g_qh[(size_t)r0*72 + k0 + 8];
            QAh[kt][3] = *(const uint32_t*)&g_qh[(size_t)(r0+8)*72 + k0 + 8];
            QAl[kt][0] = *(const uint32_t*)&g_ql[(size_t)r0*72 + k0];
            QAl[kt][1] = *(const uint32_t*)&g_ql[(size_t)(r0+8)*72 + k0];
            QAl[kt][2] = *(const uint32_t*)&g_ql[(size_t)r0*72 + k0 + 8];
            QAl[kt][3] = *(const uint32_t*)&g_ql[(size_t)(r0+8)*72 + k0 + 8];
        }
    }

    // ---- fetch 9 precomputed path logits per batch (coalesced) ----
    for (int i = tid; i < 9*64; i += 256){
        int n = i >> 6, b = i & 63;
        int node = (n < 7) ? ((1 << n) - 1 + (sg >> (6 - n)))
                           : (127 + 2*sg + (n - 7));
        fPL[n*64 + b] = g_plog[(size_t)node*2048 + b_base + b];
    }
    __syncthreads();
    if (tid < 64){
        int b = tid;
        float common = 1.f;
        #pragma unroll
        for (int e = 0; e < 6; e++){
            int bit = (sg >> (5 - e)) & 1;
            float x = fPL[e*64 + b];
            common *= fast_sigmoid(bit ? -x : x);
        }
        float s6  = fast_sigmoid(fPL[6*64 + b]);
        float s7a = fast_sigmoid(fPL[7*64 + b]);
        float s7b = fast_sigmoid(fPL[8*64 + b]);
        fPB[0*64 + b] = common * s6 * s7a;
        fPB[1*64 + b] = common * s6 * (1.f - s7a);
        fPB[2*64 + b] = common * (1.f - s6) * s7b;
        fPB[3*64 + b] = common * (1.f - s6) * (1.f - s7b);
    }

    float acc2[4][4];
    #pragma unroll
    for (int i = 0; i < 4; i++)
        #pragma unroll
        for (int j = 0; j < 4; j++) acc2[i][j] = 0.f;

    for (int si = 0; si < NS; si++){
        // ---------------- GEMM1: 4 passes of 64 n-columns ----------------
        for (int p = 0; p < 4; p++){
            int t = si*8 + p;
            if (t + 1 < total) CP_WAIT(1); else CP_WAIT(0);
            __syncthreads();
            uint32_t kb = SB + SB_BUF + (uint32_t)(t & 1)*18432;
            float a1[4][4];
            #pragma unroll
            for (int i = 0; i < 4; i++)
                #pragma unroll
                for (int j = 0; j < 4; j++) a1[i][j] = 0.f;
            #pragma unroll
            for (int kt = 0; kt < 4; kt++){
                #pragma unroll
                for (int nt = 0; nt < 4; nt++){
                    uint32_t bo = kb +
                        (uint32_t)(((grp*32 + nt*8 + (l & 7))*72 + kt*16 + (((l >> 3) & 1) << 3)) << 1);
                    uint32_t Bh[2], Bl[2]; ldsm2(Bh, bo); ldsm2(Bl, bo + 9216);
                    mma(a1[nt], QAh[kt], Bh); mma(a1[nt], QAh[kt], Bl); mma(a1[nt], QAl[kt], Bh);
                }
            }
            #pragma unroll
            for (int nt = 0; nt < 4; nt++){
                int r = bt*16 + (l >> 2);
                int cc = p*64 + grp*32 + nt*8 + 2*(l & 3);
                fT[r*257 + 1 + cc]     = a1[nt][0];
                fT[r*257 + 2 + cc]     = a1[nt][1];
                fT[(r+8)*257 + 1 + cc] = a1[nt][2];
                fT[(r+8)*257 + 2 + cc] = a1[nt][3];
            }
            __syncthreads();
            if (t + 2 < total) issue(t + 2);
        }
        if (tid < 64) fT[tid*257] = fPB[si*64 + tid];
        __syncthreads();

        // ---------------- expansion (warp-private 8 batches) ----------------
        {
            const int wb = w * 8;
            #pragma unroll
            for (int e = 0; e < 7; e++){
                int half = 1 << e;
                for (int it = l; it < 8*half; it += 32){
                    int b = wb + (it & 7), pos = it >> 3;
                    float sg0 = fast_sigmoid(fT[b*257 + half + pos]);
                    float v = fT[b*257 + pos];
                    float c0 = v * sg0;
                    fT[b*257 + pos]        = c0;
                    fT[b*257 + pos + half] = v - c0;
                }
                __syncwarp();
            }
            for (int it = l; it < 1024; it += 32){   // level 7 -> packed split
                int b = wb + (it & 7), pos = it >> 3;
                float sg0 = fast_sigmoid(fT[b*257 + 128 + pos]);
                float v = fT[b*257 + pos];
                float c0 = v * sg0, c1 = v - c0;
                uT[b*257 + pos]       = packsplit(c0);
                uT[b*257 + pos + 128] = packsplit(c1);
            }
        }
        __syncthreads();

        // ---------------- GEMM2: 4 k-chunks, register accumulator ----------------
        for (int c = 0; c < 4; c++){
            int t = si*8 + 4 + c;
            if (t + 1 < total) CP_WAIT(1); else CP_WAIT(0);
            __syncthreads();
            uint32_t vb = SB + SB_BUF + (uint32_t)(t & 1)*18432;
            #pragma unroll
            for (int kt = 0; kt < 4; kt++){
                int r0 = bt*16 + (l >> 2);
                int kk = c*64 + kt*16 + 2*(l & 3);
                uint32_t Ah[4], Al[4];
                {
                    uint32_t p0 = uT[r0*257 + kk],       p1 = uT[r0*257 + kk + 1];
                    Ah[0] = prmt(p0, p1, 0x5410); Al[0] = prmt(p0, p1, 0x7632);
                    p0 = uT[(r0+8)*257 + kk];     p1 = uT[(r0+8)*257 + kk + 1];
                    Ah[1] = prmt(p0, p1, 0x5410); Al[1] = prmt(p0, p1, 0x7632);
                    p0 = uT[r0*257 + kk + 8];     p1 = uT[r0*257 + kk + 9];
                    Ah[2] = prmt(p0, p1, 0x5410); Al[2] = prmt(p0, p1, 0x7632);
                    p0 = uT[(r0+8)*257 + kk + 8]; p1 = uT[(r0+8)*257 + kk + 9];
                    Ah[3] = prmt(p0, p1, 0x5410); Al[3] = prmt(p0, p1, 0x7632);
                }
                #pragma unroll
                for (int dt = 0; dt < 4; dt++){
                    uint32_t bo = vb +
                        (uint32_t)(((kt*16 + (l & 15))*72 + grp*32 + dt*8) << 1);
                    uint32_t Bh[2], Bl[2]; ldsm2t(Bh, bo); ldsm2t(Bl, bo + 9216);
                    mma(acc2[dt], Ah, Bh); mma(acc2[dt], Ah, Bl); mma(acc2[dt], Al, Bh);
                }
            }
            __syncthreads();
            if (t + 2 < total) issue(t + 2);
        }
    }

    // ---------------- epilogue: one atomic pass per CTA ----------------
    #pragma unroll
    for (int dt = 0; dt < 4; dt++){
        int r = b_base + bt*16 + (l >> 2);
        int cc = grp*32 + dt*8 + 2*(l & 3);
        atomicAdd(&out[(size_t)r*64 + cc],         acc2[dt][0]);
        atomicAdd(&out[(size_t)r*64 + cc + 1],     acc2[dt][1]);
        atomicAdd(&out[(size_t)(r+8)*64 + cc],     acc2[dt][2]);
        atomicAdd(&out[(size_t)(r+8)*64 + cc + 1], acc2[dt][3]);
    }
}

extern "C" void kernel_launch(void* const* d_in, const int* in_sizes, int n_in,
                              void* d_out, int out_size) {
    const float* q  = (const float*)d_in[0];
    const float* tk = (const float*)d_in[1];
    const float* tv = (const float*)d_in[2];
    float* out = (float*)d_out;

    cudaFuncSetAttribute(tree_kernel,
                         cudaFuncAttributeMaxDynamicSharedMemorySize, SMEM_BYTES);
    cudaFuncSetAttribute(prep_plog,
                         cudaFuncAttributeMaxDynamicSharedMemorySize, PLOG_SMEM);

    prep_kd<<<65536, 72>>>(tk);
    prep_v<<<65536, 72>>>(tv);
    prep_q<<<2048, 72>>>(q);
    prep_plog<<<32, 256, PLOG_SMEM>>>(q, tk);
    cudaMemsetAsync(out, 0, (size_t)2048 * 64 * sizeof(float));
    tree_kernel<<<dim3(32, 64), 256, SMEM_BYTES>>>(out);
}

// round 10
// speedup vs baseline: 1.3384x; 1.0162x over previous
#include <cuda_runtime.h>
#include <cuda_bf16.h>
#include <cstdint>

#define NS 4
// smem (bytes): T = float[64][257], 2 chunk bufs, path scratch
#define SB_BUF  65792
#define SB_PLOG 102656             // float[9*64]
#define SB_PB   104960             // float[4*64]
#define SMEM_BYTES 105984          // 2 CTAs/SM
#define PLOG_SMEM ((64*65 + 16*64) * 4)   // 20736

__device__ __align__(256) __nv_bfloat16 g_kdh[256*256*72];
__device__ __align__(256) __nv_bfloat16 g_kdl[256*256*72];
__device__ __align__(256) __nv_bfloat16 g_vh [256*256*72];
__device__ __align__(256) __nv_bfloat16 g_vl [256*256*72];
__device__ __align__(256) __nv_bfloat16 g_qh [2048*72];
__device__ __align__(256) __nv_bfloat16 g_ql [2048*72];
__device__ float g_plog[255*2048];  // fp32 logits, top-255 nodes

__device__ __forceinline__ uint32_t cvta(const void* p){
    uint32_t a; asm("{.reg .u64 t; cvta.to.shared.u64 t,%1; cvt.u32.u64 %0,t;}":"=r"(a):"l"(p)); return a;
}
__device__ __forceinline__ void ldsm2(uint32_t r[2], uint32_t a){
    asm volatile("ldmatrix.sync.aligned.m8n8.x2.shared.b16 {%0,%1},[%2];"
        :"=r"(r[0]),"=r"(r[1]):"r"(a));
}
__device__ __forceinline__ void ldsm2t(uint32_t r[2], uint32_t a){
    asm volatile("ldmatrix.sync.aligned.m8n8.x2.trans.shared.b16 {%0,%1},[%2];"
        :"=r"(r[0]),"=r"(r[1]):"r"(a));
}
__device__ __forceinline__ void mma(float c[4], const uint32_t a[4], const uint32_t b[2]){
    asm volatile("mma.sync.aligned.m16n8k16.row.col.f32.bf16.bf16.f32 "
        "{%0,%1,%2,%3},{%4,%5,%6,%7},{%8,%9},{%0,%1,%2,%3};"
        :"+f"(c[0]),"+f"(c[1]),"+f"(c[2]),"+f"(c[3])
        :"r"(a[0]),"r"(a[1]),"r"(a[2]),"r"(a[3]),"r"(b[0]),"r"(b[1]));
}
__device__ __forceinline__ uint32_t prmt(uint32_t a, uint32_t b, uint32_t s){
    uint32_t r; asm("prmt.b32 %0,%1,%2,%3;":"=r"(r):"r"(a),"r"(b),"r"(s)); return r;
}
__device__ __forceinline__ void cp16(uint32_t d, const void* s){
    asm volatile("cp.async.cg.shared.global [%0],[%1],16;"::"r"(d),"l"(s));
}
#define CP_COMMIT() asm volatile("cp.async.commit_group;":::"memory")
#define CP_WAIT(N)  asm volatile("cp.async.wait_group %0;"::"n"(N):"memory")
__device__ __forceinline__ void split2(float x, __nv_bfloat16& h, __nv_bfloat16& lo){
    h = __float2bfloat16(x); lo = __float2bfloat16(x - __bfloat162float(h));
}
__device__ __forceinline__ uint32_t packsplit(float x){
    __nv_bfloat16 h, lo; split2(x, h, lo);
    return (uint32_t)__bfloat16_as_ushort(h) | ((uint32_t)__bfloat16_as_ushort(lo) << 16);
}
__device__ __forceinline__ float fast_sigmoid(float x){
    float e; asm("ex2.approx.f32 %0,%1;":"=f"(e):"f"(-x*1.4426950408889634f));
    float r; asm("rcp.approx.f32 %0,%1;":"=f"(r):"f"(1.f+e));
    return r;
}

// ------------------- fused prep: KD | V | Q | PLOG -------------------
// blocks [0,16384)            : KD split images, 4 rows/block
// blocks [16384,32768)        : V  split images, 4 rows/block
// blocks [32768,33280)        : Q  split, 4 batches/block
// blocks [33280,33792)        : path logits, 32 btiles x 16 node-slices
__global__ __launch_bounds__(256)
void prep_all(const float* __restrict__ q, const float* __restrict__ tk,
              const float* __restrict__ tv)
{
    const int bid = blockIdx.x, tid = threadIdx.x;
    const int lr = tid >> 6, k = tid & 63;

    if (bid < 16384){                       // ---- KD ----
        int gr = bid*4 + lr;                // (s<<8)|r
        int s = gr >> 8, r = gr & 255;
        float d = 0.f;
        if (r < 255){
            int rp = r+1, e = 31-__clz(rp), pj = rp-(1<<e);
            int j = e ? (int)(__brev((unsigned)pj) >> (32-e)) : 0;
            size_t node = (((size_t)1<<(e+8))-1) + (size_t)s*(1<<e) + j;
            d = tk[node*128 + k] - tk[node*128 + 64 + k];
        }
        __nv_bfloat16 h, lo; split2(d, h, lo);
        g_kdh[(size_t)gr*72 + k] = h; g_kdl[(size_t)gr*72 + k] = lo;
    } else if (bid < 32768){                // ---- V ----
        int gr = (bid - 16384)*4 + lr;
        int s = gr >> 8, r = gr & 255;
        size_t leaf = (size_t)s*256 + (__brev((unsigned)r) >> 24);
        float v = tv[leaf*64 + k];
        __nv_bfloat16 h, lo; split2(v, h, lo);
        g_vh[(size_t)gr*72 + k] = h; g_vl[(size_t)gr*72 + k] = lo;
    } else if (bid < 33280){                // ---- Q ----
        int b = (bid - 32768)*4 + lr;
        __nv_bfloat16 h, lo; split2(q[(size_t)b*64 + k], h, lo);
        g_qh[(size_t)b*72 + k] = h; g_ql[(size_t)b*72 + k] = lo;
    } else {                                // ---- PLOG ----
        extern __shared__ float ps[];
        float* qs = ps;                     // [k][b] stride 65
        float* ks = ps + 64*65;             // [j][k] 16 nodes
        int pb = bid - 33280;
        int btile = pb >> 4, slice = pb & 15;
        int b_base = btile * 64, n0 = slice * 16;
        for (int i = tid; i < 64*64; i += 256){
            int b = i >> 6, kk = i & 63;
            qs[kk*65 + b] = q[(size_t)(b_base + b)*64 + kk];
        }
        for (int i = tid; i < 16*64; i += 256){
            int j = i >> 6, kk = i & 63;
            int n = n0 + j;
            ks[i] = (n < 255) ? (tk[(size_t)n*128 + kk] - tk[(size_t)n*128 + 64 + kk]) : 0.f;
        }
        __syncthreads();
        int b = tid & 63, sub = tid >> 6;
        #pragma unroll
        for (int j2 = 0; j2 < 4; j2++){
            int j = sub*4 + j2, n = n0 + j;
            if (n >= 255) break;
            float acc = 0.f;
            #pragma unroll 16
            for (int kk = 0; kk < 64; kk++)
                acc = fmaf(qs[kk*65 + b], ks[j*64 + kk], acc);
            g_plog[(size_t)n*2048 + b_base + b] = acc;
        }
    }
}

// ----------------------------- main kernel -----------------------------
__global__ __launch_bounds__(256, 2)
void tree_kernel(float* __restrict__ out)
{
    extern __shared__ char smc[];
    float* fT = (float*)smc;
    uint32_t* uT = (uint32_t*)smc;
    float* fPL = (float*)(smc + SB_PLOG);
    float* fPB = (float*)(smc + SB_PB);
    const uint32_t SB = cvta(smc);
    const int tid = threadIdx.x, w = tid >> 5, l = tid & 31;
    const int btile = blockIdx.x, sg = blockIdx.y;
    const int b_base = btile * 64;
    const int bt = w & 3, grp = w >> 2;
    const int total = NS * 8;

    auto issue = [&](int t){
        if (t >= total) return;
        int c = t & 7, si = t >> 3;
        size_t off = ((size_t)(sg*NS + si)*256 + (size_t)(c & 3)*64)*72;
        const __nv_bfloat16 *ph = (c < 4) ? g_kdh + off : g_vh + off;
        const __nv_bfloat16 *pl = (c < 4) ? g_kdl + off : g_vl + off;
        uint32_t dst = SB + SB_BUF + (uint32_t)(t & 1)*18432;
        for (int i = tid; i < 576; i += 256){
            cp16(dst + i*16,        (const char*)ph + i*16);
            cp16(dst + 9216 + i*16, (const char*)pl + i*16);
        }
        CP_COMMIT();
    };

    issue(0); issue(1);

    // ---- Q fragments -> registers ----
    uint32_t QAh[4][4], QAl[4][4];
    {
        int r0 = b_base + bt*16 + (l >> 2);
        int c0 = 2 * (l & 3);
        #pragma unroll
        for (int kt = 0; kt < 4; kt++){
            int k0 = kt*16 + c0;
            QAh[kt][0] = *(const uint32_t*)&g_qh[(size_t)r0*72 + k0];
            QAh[kt][1] = *(const uint32_t*)&g_qh[(size_t)(r0+8)*72 + k0];
            QAh[kt][2] = *(const uint32_t*)&g_qh[(size_t)r0*72 + k0 + 8];
            QAh[kt][3] = *(const uint32_t*)&g_qh[(size_t)(r0+8)*72 + k0 + 8];
            QAl[kt][0] = *(const uint32_t*)&g_ql[(size_t)r0*72 + k0];
            QAl[kt][1] = *(const uint32_t*)&g_ql[(size_t)(r0+8)*72 + k0];
            QAl[kt][2] = *(const uint32_t*)&g_ql[(size_t)r0*72 + k0 + 8];
            QAl[kt][3] = *(const uint32_t*)&g_ql[(size_t)(r0+8)*72 + k0 + 8];
        }
    }

    // ---- fetch 9 precomputed path logits per batch (coalesced) ----
    for (int i = tid; i < 9*64; i += 256){
        int n = i >> 6, b = i & 63;
        int node = (n < 7) ? ((1 << n) - 1 + (sg >> (6 - n)))
                           : (127 + 2*sg + (n - 7));
        fPL[n*64 + b] = g_plog[(size_t)node*2048 + b_base + b];
    }
    __syncthreads();
    if (tid < 64){
        int b = tid;
        float common = 1.f;
        #pragma unroll
        for (int e = 0; e < 6; e++){
            int bit = (sg >> (5 - e)) & 1;
            float x = fPL[e*64 + b];
            common *= fast_sigmoid(bit ? -x : x);
        }
        float s6  = fast_sigmoid(fPL[6*64 + b]);
        float s7a = fast_sigmoid(fPL[7*64 + b]);
        float s7b = fast_sigmoid(fPL[8*64 + b]);
        fPB[0*64 + b] = common * s6 * s7a;
        fPB[1*64 + b] = common * s6 * (1.f - s7a);
        fPB[2*64 + b] = common * (1.f - s6) * s7b;
        fPB[3*64 + b] = common * (1.f - s6) * (1.f - s7b);
    }

    float acc2[4][4];
    #pragma unroll
    for (int i = 0; i < 4; i++)
        #pragma unroll
        for (int j = 0; j < 4; j++) acc2[i][j] = 0.f;

    for (int si = 0; si < NS; si++){
        // ---------------- GEMM1: 4 passes of 64 n-columns ----------------
        for (int p = 0; p < 4; p++){
            int t = si*8 + p;
            if (t + 1 < total) CP_WAIT(1); else CP_WAIT(0);
            __syncthreads();
            uint32_t kb = SB + SB_BUF + (uint32_t)(t & 1)*18432;
            float a1[4][4];
            #pragma unroll
            for (int i = 0; i < 4; i++)
                #pragma unroll
                for (int j = 0; j < 4; j++) a1[i][j] = 0.f;
            #pragma unroll
            for (int kt = 0; kt < 4; kt++){
                #pragma unroll
                for (int nt = 0; nt < 4; nt++){
                    uint32_t bo = kb +
                        (uint32_t)(((grp*32 + nt*8 + (l & 7))*72 + kt*16 + (((l >> 3) & 1) << 3)) << 1);
                    uint32_t Bh[2], Bl[2]; ldsm2(Bh, bo); ldsm2(Bl, bo + 9216);
                    mma(a1[nt], QAh[kt], Bh); mma(a1[nt], QAh[kt], Bl); mma(a1[nt], QAl[kt], Bh);
                }
            }
            #pragma unroll
            for (int nt = 0; nt < 4; nt++){
                int r = bt*16 + (l >> 2);
                int cc = p*64 + grp*32 + nt*8 + 2*(l & 3);
                fT[r*257 + 1 + cc]     = a1[nt][0];
                fT[r*257 + 2 + cc]     = a1[nt][1];
                fT[(r+8)*257 + 1 + cc] = a1[nt][2];
                fT[(r+8)*257 + 2 + cc] = a1[nt][3];
            }
            __syncthreads();
            if (t + 2 < total) issue(t + 2);
        }

        // ---------------- sigma precompute: logits -> sigmoids in place ----------------
        for (int it = tid; it < 64*255; it += 256){
            int b = it & 63, slot = 1 + (it >> 6);
            fT[b*257 + slot] = fast_sigmoid(fT[b*257 + slot]);
        }
        if (tid < 64) fT[tid*257] = fPB[si*64 + tid];
        __syncthreads();

        // ---------------- expansion (warp-private 8 batches, no MUFU) ----------------
        {
            const int wb = w * 8;
            #pragma unroll
            for (int e = 0; e < 7; e++){
                int half = 1 << e;
                for (int it = l; it < 8*half; it += 32){
                    int b = wb + (it & 7), pos = it >> 3;
                    float sg0 = fT[b*257 + half + pos];
                    float v = fT[b*257 + pos];
                    float c0 = v * sg0;
                    fT[b*257 + pos]        = c0;
                    fT[b*257 + pos + half] = v - c0;
                }
                __syncwarp();
            }
            for (int it = l; it < 1024; it += 32){   // level 7 -> packed split
                int b = wb + (it & 7), pos = it >> 3;
                float sg0 = fT[b*257 + 128 + pos];
                float v = fT[b*257 + pos];
                float c0 = v * sg0, c1 = v - c0;
                uT[b*257 + pos]       = packsplit(c0);
                uT[b*257 + pos + 128] = packsplit(c1);
            }
        }
        __syncthreads();

        // ---------------- GEMM2: 4 k-chunks, register accumulator ----------------
        for (int c = 0; c < 4; c++){
            int t = si*8 + 4 + c;
            if (t + 1 < total) CP_WAIT(1); else CP_WAIT(0);
            __syncthreads();
            uint32_t vb = SB + SB_BUF + (uint32_t)(t & 1)*18432;
            #pragma unroll
            for (int kt = 0; kt < 4; kt++){
                int r0 = bt*16 + (l >> 2);
                int kk = c*64 + kt*16 + 2*(l & 3);
                uint32_t Ah[4], Al[4];
                {
                    uint32_t p0 = uT[r0*257 + kk],       p1 = uT[r0*257 + kk + 1];
                    Ah[0] = prmt(p0, p1, 0x5410); Al[0] = prmt(p0, p1, 0x7632);
                    p0 = uT[(r0+8)*257 + kk];     p1 = uT[(r0+8)*257 + kk + 1];
                    Ah[1] = prmt(p0, p1, 0x5410); Al[1] = prmt(p0, p1, 0x7632);
                    p0 = uT[r0*257 + kk + 8];     p1 = uT[r0*257 + kk + 9];
                    Ah[2] = prmt(p0, p1, 0x5410); Al[2] = prmt(p0, p1, 0x7632);
                    p0 = uT[(r0+8)*257 + kk + 8]; p1 = uT[(r0+8)*257 + kk + 9];
                    Ah[3] = prmt(p0, p1, 0x5410); Al[3] = prmt(p0, p1, 0x7632);
                }
                #pragma unroll
                for (int dt = 0; dt < 4; dt++){
                    uint32_t bo = vb +
                        (uint32_t)(((kt*16 + (l & 15))*72 + grp*32 + dt*8) << 1);
                    uint32_t Bh[2], Bl[2]; ldsm2t(Bh, bo); ldsm2t(Bl, bo + 9216);
                    mma(acc2[dt], Ah, Bh); mma(acc2[dt], Ah, Bl); mma(acc2[dt], Al, Bh);
                }
            }
            __syncthreads();
            if (t + 2 < total) issue(t + 2);
        }
    }

    // ---------------- epilogue: one atomic pass per CTA ----------------
    #pragma unroll
    for (int dt = 0; dt < 4; dt++){
        int r = b_base + bt*16 + (l >> 2);
        int cc = grp*32 + dt*8 + 2*(l & 3);
        atomicAdd(&out[(size_t)r*64 + cc],         acc2[dt][0]);
        atomicAdd(&out[(size_t)r*64 + cc + 1],     acc2[dt][1]);
        atomicAdd(&out[(size_t)(r+8)*64 + cc],     acc2[dt][2]);
        atomicAdd(&out[(size_t)(r+8)*64 + cc + 1], acc2[dt][3]);
    }
}

extern "C" void kernel_launch(void* const* d_in, const int* in_sizes, int n_in,
                              void* d_out, int out_size) {
    const float* q  = (const float*)d_in[0];
    const float* tk = (const float*)d_in[1];
    const float* tv = (const float*)d_in[2];
    float* out = (float*)d_out;

    cudaFuncSetAttribute(tree_kernel,
                         cudaFuncAttributeMaxDynamicSharedMemorySize, SMEM_BYTES);

    prep_all<<<33792, 256, PLOG_SMEM>>>(q, tk, tv);
    cudaMemsetAsync(out, 0, (size_t)2048 * 64 * sizeof(float));
    tree_kernel<<<dim3(32, 64), 256, SMEM_BYTES>>>(out);
}

// round 11
// speedup vs baseline: 1.4345x; 1.0718x over previous
#include <cuda_runtime.h>
#include <cuda_bf16.h>
#include <cstdint>

#define NS 4
// smem (bytes): T = float[64][257], 2 chunk bufs, path scratch
#define SB_BUF  65792
#define SB_PLOG 102656             // float[9*64]
#define SB_PB   104960             // float[4*64]
#define SMEM_BYTES 105984          // 2 CTAs/SM
#define PLOG_SMEM ((64*65 + 16*64) * 4)   // 20736

__device__ __align__(256) __nv_bfloat16 g_kdh[256*256*72];
__device__ __align__(256) __nv_bfloat16 g_kdl[256*256*72];
__device__ __align__(256) __nv_bfloat16 g_vh [256*256*72];
__device__ __align__(256) __nv_bfloat16 g_vl [256*256*72];
__device__ __align__(256) __nv_bfloat16 g_qh [2048*72];
__device__ __align__(256) __nv_bfloat16 g_ql [2048*72];
__device__ float g_plog[255*2048];  // fp32 logits, top-255 nodes

__device__ __forceinline__ uint32_t cvta(const void* p){
    uint32_t a; asm("{.reg .u64 t; cvta.to.shared.u64 t,%1; cvt.u32.u64 %0,t;}":"=r"(a):"l"(p)); return a;
}
__device__ __forceinline__ void ldsm4(uint32_t r[4], uint32_t a){
    asm volatile("ldmatrix.sync.aligned.m8n8.x4.shared.b16 {%0,%1,%2,%3},[%4];"
        :"=r"(r[0]),"=r"(r[1]),"=r"(r[2]),"=r"(r[3]):"r"(a));
}
__device__ __forceinline__ void ldsm4t(uint32_t r[4], uint32_t a){
    asm volatile("ldmatrix.sync.aligned.m8n8.x4.trans.shared.b16 {%0,%1,%2,%3},[%4];"
        :"=r"(r[0]),"=r"(r[1]),"=r"(r[2]),"=r"(r[3]):"r"(a));
}
__device__ __forceinline__ void mma(float c[4], const uint32_t a[4], const uint32_t b0, const uint32_t b1){
    asm volatile("mma.sync.aligned.m16n8k16.row.col.f32.bf16.bf16.f32 "
        "{%0,%1,%2,%3},{%4,%5,%6,%7},{%8,%9},{%0,%1,%2,%3};"
        :"+f"(c[0]),"+f"(c[1]),"+f"(c[2]),"+f"(c[3])
        :"r"(a[0]),"r"(a[1]),"r"(a[2]),"r"(a[3]),"r"(b0),"r"(b1));
}
__device__ __forceinline__ uint32_t prmt(uint32_t a, uint32_t b, uint32_t s){
    uint32_t r; asm("prmt.b32 %0,%1,%2,%3;":"=r"(r):"r"(a),"r"(b),"r"(s)); return r;
}
__device__ __forceinline__ void cp16(uint32_t d, const void* s){
    asm volatile("cp.async.cg.shared.global [%0],[%1],16;"::"r"(d),"l"(s));
}
#define CP_COMMIT() asm volatile("cp.async.commit_group;":::"memory")
#define CP_WAIT(N)  asm volatile("cp.async.wait_group %0;"::"n"(N):"memory")
__device__ __forceinline__ void split2(float x, __nv_bfloat16& h, __nv_bfloat16& lo){
    h = __float2bfloat16(x); lo = __float2bfloat16(x - __bfloat162float(h));
}
__device__ __forceinline__ uint32_t packsplit(float x){
    __nv_bfloat16 h, lo; split2(x, h, lo);
    return (uint32_t)__bfloat16_as_ushort(h) | ((uint32_t)__bfloat16_as_ushort(lo) << 16);
}
__device__ __forceinline__ float fast_sigmoid(float x){
    float e; asm("ex2.approx.f32 %0,%1;":"=f"(e):"f"(-x*1.4426950408889634f));
    float r; asm("rcp.approx.f32 %0,%1;":"=f"(r):"f"(1.f+e));
    return r;
}

// ------------------- fused prep: KD | V | Q | PLOG -------------------
__global__ __launch_bounds__(256)
void prep_all(const float* __restrict__ q, const float* __restrict__ tk,
              const float* __restrict__ tv)
{
    const int bid = blockIdx.x, tid = threadIdx.x;
    const int lr = tid >> 6, k = tid & 63;

    if (bid < 16384){                       // ---- KD ----
        int gr = bid*4 + lr;
        int s = gr >> 8, r = gr & 255;
        float d = 0.f;
        if (r < 255){
            int rp = r+1, e = 31-__clz(rp), pj = rp-(1<<e);
            int j = e ? (int)(__brev((unsigned)pj) >> (32-e)) : 0;
            size_t node = (((size_t)1<<(e+8))-1) + (size_t)s*(1<<e) + j;
            d = tk[node*128 + k] - tk[node*128 + 64 + k];
        }
        __nv_bfloat16 h, lo; split2(d, h, lo);
        g_kdh[(size_t)gr*72 + k] = h; g_kdl[(size_t)gr*72 + k] = lo;
    } else if (bid < 32768){                // ---- V ----
        int gr = (bid - 16384)*4 + lr;
        int s = gr >> 8, r = gr & 255;
        size_t leaf = (size_t)s*256 + (__brev((unsigned)r) >> 24);
        float v = tv[leaf*64 + k];
        __nv_bfloat16 h, lo; split2(v, h, lo);
        g_vh[(size_t)gr*72 + k] = h; g_vl[(size_t)gr*72 + k] = lo;
    } else if (bid < 33280){                // ---- Q ----
        int b = (bid - 32768)*4 + lr;
        __nv_bfloat16 h, lo; split2(q[(size_t)b*64 + k], h, lo);
        g_qh[(size_t)b*72 + k] = h; g_ql[(size_t)b*72 + k] = lo;
    } else {                                // ---- PLOG ----
        extern __shared__ float ps[];
        float* qs = ps;                     // [k][b] stride 65
        float* ks = ps + 64*65;             // [j][k] 16 nodes
        int pb = bid - 33280;
        int btile = pb >> 4, slice = pb & 15;
        int b_base = btile * 64, n0 = slice * 16;
        for (int i = tid; i < 64*64; i += 256){
            int b = i >> 6, kk = i & 63;
            qs[kk*65 + b] = q[(size_t)(b_base + b)*64 + kk];
        }
        for (int i = tid; i < 16*64; i += 256){
            int j = i >> 6, kk = i & 63;
            int n = n0 + j;
            ks[i] = (n < 255) ? (tk[(size_t)n*128 + kk] - tk[(size_t)n*128 + 64 + kk]) : 0.f;
        }
        __syncthreads();
        int b = tid & 63, sub = tid >> 6;
        #pragma unroll
        for (int j2 = 0; j2 < 4; j2++){
            int j = sub*4 + j2, n = n0 + j;
            if (n >= 255) break;
            float acc = 0.f;
            #pragma unroll 16
            for (int kk = 0; kk < 64; kk++)
                acc = fmaf(qs[kk*65 + b], ks[j*64 + kk], acc);
            g_plog[(size_t)n*2048 + b_base + b] = acc;
        }
    }
}

// ----------------------------- main kernel -----------------------------
__global__ __launch_bounds__(256, 2)
void tree_kernel(float* __restrict__ out)
{
    extern __shared__ char smc[];
    float* fT = (float*)smc;
    uint32_t* uT = (uint32_t*)smc;
    float* fPL = (float*)(smc + SB_PLOG);
    float* fPB = (float*)(smc + SB_PB);
    const uint32_t SB = cvta(smc);
    const int tid = threadIdx.x, w = tid >> 5, l = tid & 31;
    const int btile = blockIdx.x, sg = blockIdx.y;
    const int b_base = btile * 64;
    const int bt = w & 3, grp = w >> 2;
    const int total = NS * 8;

    auto issue = [&](int t){
        if (t >= total) return;
        int c = t & 7, si = t >> 3;
        size_t off = ((size_t)(sg*NS + si)*256 + (size_t)(c & 3)*64)*72;
        const __nv_bfloat16 *ph = (c < 4) ? g_kdh + off : g_vh + off;
        const __nv_bfloat16 *pl = (c < 4) ? g_kdl + off : g_vl + off;
        uint32_t dst = SB + SB_BUF + (uint32_t)(t & 1)*18432;
        for (int i = tid; i < 576; i += 256){
            cp16(dst + i*16,        (const char*)ph + i*16);
            cp16(dst + 9216 + i*16, (const char*)pl + i*16);
        }
        CP_COMMIT();
    };

    issue(0); issue(1);

    // ---- Q fragments -> registers ----
    uint32_t QAh[4][4], QAl[4][4];
    {
        int r0 = b_base + bt*16 + (l >> 2);
        int c0 = 2 * (l & 3);
        #pragma unroll
        for (int kt = 0; kt < 4; kt++){
            int k0 = kt*16 + c0;
            QAh[kt][0] = *(const uint32_t*)&g_qh[(size_t)r0*72 + k0];
            QAh[kt][1] = *(const uint32_t*)&g_qh[(size_t)(r0+8)*72 + k0];
            QAh[kt][2] = *(const uint32_t*)&g_qh[(size_t)r0*72 + k0 + 8];
            QAh[kt][3] = *(const uint32_t*)&g_qh[(size_t)(r0+8)*72 + k0 + 8];
            QAl[kt][0] = *(const uint32_t*)&g_ql[(size_t)r0*72 + k0];
            QAl[kt][1] = *(const uint32_t*)&g_ql[(size_t)(r0+8)*72 + k0];
            QAl[kt][2] = *(const uint32_t*)&g_ql[(size_t)r0*72 + k0 + 8];
            QAl[kt][3] = *(const uint32_t*)&g_ql[(size_t)(r0+8)*72 + k0 + 8];
        }
    }

    // ---- 9 precomputed path logits per batch (coalesced) -> base probs ----
    for (int i = tid; i < 9*64; i += 256){
        int n = i >> 6, b = i & 63;
        int node = (n < 7) ? ((1 << n) - 1 + (sg >> (6 - n)))
                           : (127 + 2*sg + (n - 7));
        fPL[n*64 + b] = g_plog[(size_t)node*2048 + b_base + b];
    }
    __syncthreads();
    if (tid < 64){
        int b = tid;
        float common = 1.f;
        #pragma unroll
        for (int e = 0; e < 6; e++){
            int bit = (sg >> (5 - e)) & 1;
            float x = fPL[e*64 + b];
            common *= fast_sigmoid(bit ? -x : x);
        }
        float s6  = fast_sigmoid(fPL[6*64 + b]);
        float s7a = fast_sigmoid(fPL[7*64 + b]);
        float s7b = fast_sigmoid(fPL[8*64 + b]);
        fPB[0*64 + b] = common * s6 * s7a;
        fPB[1*64 + b] = common * s6 * (1.f - s7a);
        fPB[2*64 + b] = common * (1.f - s6) * s7b;
        fPB[3*64 + b] = common * (1.f - s6) * (1.f - s7b);
    }

    float acc2[4][4];
    #pragma unroll
    for (int i = 0; i < 4; i++)
        #pragma unroll
        for (int j = 0; j < 4; j++) acc2[i][j] = 0.f;

    for (int si = 0; si < NS; si++){
        // ---------------- GEMM1: 4 passes of 64 n-columns ----------------
        for (int p = 0; p < 4; p++){
            int t = si*8 + p;
            if (t + 1 < total) CP_WAIT(1); else CP_WAIT(0);
            __syncthreads();
            uint32_t kb = SB + SB_BUF + (uint32_t)(t & 1)*18432;
            float a1[4][4];
            #pragma unroll
            for (int i = 0; i < 4; i++)
                #pragma unroll
                for (int j = 0; j < 4; j++) a1[i][j] = 0.f;
            #pragma unroll
            for (int kt = 0; kt < 4; kt++){
                #pragma unroll
                for (int ntp = 0; ntp < 2; ntp++){
                    // x4: lanes 0-7 mat0 (n-tile A,k0-7), 8-15 mat1 (A,k8-15),
                    //     16-23 mat2 (B,k0-7), 24-31 mat3 (B,k8-15)
                    uint32_t bo = kb + (uint32_t)((
                        (grp*32 + ntp*16 + (((l >> 4) & 1) << 3) + (l & 7))*72
                        + kt*16 + (((l >> 3) & 1) << 3)) << 1);
                    uint32_t Bh[4], Bl[4];
                    ldsm4(Bh, bo); ldsm4(Bl, bo + 9216);
                    mma(a1[2*ntp],   QAh[kt], Bh[0], Bh[1]);
                    mma(a1[2*ntp],   QAh[kt], Bl[0], Bl[1]);
                    mma(a1[2*ntp],   QAl[kt], Bh[0], Bh[1]);
                    mma(a1[2*ntp+1], QAh[kt], Bh[2], Bh[3]);
                    mma(a1[2*ntp+1], QAh[kt], Bl[2], Bl[3]);
                    mma(a1[2*ntp+1], QAl[kt], Bh[2], Bh[3]);
                }
            }
            // sigma fused into epilogue: store sigma(logit) into T slots
            #pragma unroll
            for (int nt = 0; nt < 4; nt++){
                int r = bt*16 + (l >> 2);
                int cc = p*64 + grp*32 + nt*8 + 2*(l & 3);
                fT[r*257 + 1 + cc]     = fast_sigmoid(a1[nt][0]);
                fT[r*257 + 2 + cc]     = fast_sigmoid(a1[nt][1]);
                fT[(r+8)*257 + 1 + cc] = fast_sigmoid(a1[nt][2]);
                fT[(r+8)*257 + 2 + cc] = fast_sigmoid(a1[nt][3]);
            }
            __syncthreads();
            if (t + 2 < total) issue(t + 2);
        }
        if (tid < 64) fT[tid*257] = fPB[si*64 + tid];
        __syncthreads();

        // ---------------- expansion (warp-private 8 batches, no MUFU) ----------------
        {
            const int wb = w * 8;
            #pragma unroll
            for (int e = 0; e < 7; e++){
                int half = 1 << e;
                for (int it = l; it < 8*half; it += 32){
                    int b = wb + (it & 7), pos = it >> 3;
                    float sg0 = fT[b*257 + half + pos];
                    float v = fT[b*257 + pos];
                    float c0 = v * sg0;
                    fT[b*257 + pos]        = c0;
                    fT[b*257 + pos + half] = v - c0;
                }
                __syncwarp();
            }
            for (int it = l; it < 1024; it += 32){   // level 7 -> packed split
                int b = wb + (it & 7), pos = it >> 3;
                float sg0 = fT[b*257 + 128 + pos];
                float v = fT[b*257 + pos];
                float c0 = v * sg0, c1 = v - c0;
                uT[b*257 + pos]       = packsplit(c0);
                uT[b*257 + pos + 128] = packsplit(c1);
            }
        }
        __syncthreads();

        // ---------------- GEMM2: 4 k-chunks, register accumulator ----------------
        for (int c = 0; c < 4; c++){
            int t = si*8 + 4 + c;
            if (t + 1 < total) CP_WAIT(1); else CP_WAIT(0);
            __syncthreads();
            uint32_t vb = SB + SB_BUF + (uint32_t)(t & 1)*18432;
            #pragma unroll
            for (int kt = 0; kt < 4; kt++){
                int r0 = bt*16 + (l >> 2);
                int kk = c*64 + kt*16 + 2*(l & 3);
                uint32_t Ah[4], Al[4];
                {
                    uint32_t p0 = uT[r0*257 + kk],       p1 = uT[r0*257 + kk + 1];
                    Ah[0] = prmt(p0, p1, 0x5410); Al[0] = prmt(p0, p1, 0x7632);
                    p0 = uT[(r0+8)*257 + kk];     p1 = uT[(r0+8)*257 + kk + 1];
                    Ah[1] = prmt(p0, p1, 0x5410); Al[1] = prmt(p0, p1, 0x7632);
                    p0 = uT[r0*257 + kk + 8];     p1 = uT[r0*257 + kk + 9];
                    Ah[2] = prmt(p0, p1, 0x5410); Al[2] = prmt(p0, p1, 0x7632);
                    p0 = uT[(r0+8)*257 + kk + 8]; p1 = uT[(r0+8)*257 + kk + 9];
                    Ah[3] = prmt(p0, p1, 0x5410); Al[3] = prmt(p0, p1, 0x7632);
                }
                #pragma unroll
                for (int dtp = 0; dtp < 2; dtp++){
                    // x4 trans: lanes 0-15 d-tile A (k0-15), 16-31 d-tile B
                    uint32_t bo = vb + (uint32_t)((
                        (kt*16 + (((l >> 3) & 1) << 3) + (l & 7))*72
                        + grp*32 + dtp*16 + (((l >> 4) & 1) << 3)) << 1);
                    uint32_t Bh[4], Bl[4];
                    ldsm4t(Bh, bo); ldsm4t(Bl, bo + 9216);
                    mma(acc2[2*dtp],   Ah, Bh[0], Bh[1]);
                    mma(acc2[2*dtp],   Ah, Bl[0], Bl[1]);
                    mma(acc2[2*dtp],   Al, Bh[0], Bh[1]);
                    mma(acc2[2*dtp+1], Ah, Bh[2], Bh[3]);
                    mma(acc2[2*dtp+1], Ah, Bl[2], Bl[3]);
                    mma(acc2[2*dtp+1], Al, Bh[2], Bh[3]);
                }
            }
            __syncthreads();
            if (t + 2 < total) issue(t + 2);
        }
    }

    // ---------------- epilogue: one atomic pass per CTA ----------------
    #pragma unroll
    for (int dt = 0; dt < 4; dt++){
        int r = b_base + bt*16 + (l >> 2);
        int cc = grp*32 + dt*8 + 2*(l & 3);
        atomicAdd(&out[(size_t)r*64 + cc],         acc2[dt][0]);
        atomicAdd(&out[(size_t)r*64 + cc + 1],     acc2[dt][1]);
        atomicAdd(&out[(size_t)(r+8)*64 + cc],     acc2[dt][2]);
        atomicAdd(&out[(size_t)(r+8)*64 + cc + 1], acc2[dt][3]);
    }
}

extern "C" void kernel_launch(void* const* d_in, const int* in_sizes, int n_in,
                              void* d_out, int out_size) {
    const float* q  = (const float*)d_in[0];
    const float* tk = (const float*)d_in[1];
    const float* tv = (const float*)d_in[2];
    float* out = (float*)d_out;

    cudaFuncSetAttribute(tree_kernel,
                         cudaFuncAttributeMaxDynamicSharedMemorySize, SMEM_BYTES);

    cudaMemsetAsync(out, 0, (size_t)2048 * 64 * sizeof(float));
    prep_all<<<33792, 256, PLOG_SMEM>>>(q, tk, tv);
    tree_kernel<<<dim3(32, 64), 256, SMEM_BYTES>>>(out);
}

// round 12
// speedup vs baseline: 2.0910x; 1.4576x over previous
#include <cuda_runtime.h>
#include <cuda_bf16.h>
#include <cstdint>

#define NS 4
// smem (bytes): T = float[257 slots][72], 2 chunk bufs, base-prob scratch
#define SB_BUF  74016              // T = 257*72*4
#define SB_PB   110880             // float[4*64]
#define SMEM_BYTES 111904          // 2 CTAs/SM (<=113664)
#define PLOG_SMEM ((64*65 + 16*64) * 4)   // 20736

__device__ __align__(256) __nv_bfloat16 g_kdh[256*256*72];
__device__ __align__(256) __nv_bfloat16 g_kdl[256*256*72];
__device__ __align__(256) __nv_bfloat16 g_vh [256*256*72];
__device__ __align__(256) __nv_bfloat16 g_vl [256*256*72];
__device__ __align__(256) __nv_bfloat16 g_qh [2048*72];
__device__ __align__(256) __nv_bfloat16 g_ql [2048*72];
__device__ float g_plog[255*2048];  // fp32 logits, top-255 nodes

__device__ __forceinline__ uint32_t cvta(const void* p){
    uint32_t a; asm("{.reg .u64 t; cvta.to.shared.u64 t,%1; cvt.u32.u64 %0,t;}":"=r"(a):"l"(p)); return a;
}
__device__ __forceinline__ void ldsm4(uint32_t r[4], uint32_t a){
    asm volatile("ldmatrix.sync.aligned.m8n8.x4.shared.b16 {%0,%1,%2,%3},[%4];"
        :"=r"(r[0]),"=r"(r[1]),"=r"(r[2]),"=r"(r[3]):"r"(a));
}
__device__ __forceinline__ void ldsm4t(uint32_t r[4], uint32_t a){
    asm volatile("ldmatrix.sync.aligned.m8n8.x4.trans.shared.b16 {%0,%1,%2,%3},[%4];"
        :"=r"(r[0]),"=r"(r[1]),"=r"(r[2]),"=r"(r[3]):"r"(a));
}
__device__ __forceinline__ void mma(float c[4], const uint32_t a[4], const uint32_t b0, const uint32_t b1){
    asm volatile("mma.sync.aligned.m16n8k16.row.col.f32.bf16.bf16.f32 "
        "{%0,%1,%2,%3},{%4,%5,%6,%7},{%8,%9},{%0,%1,%2,%3};"
        :"+f"(c[0]),"+f"(c[1]),"+f"(c[2]),"+f"(c[3])
        :"r"(a[0]),"r"(a[1]),"r"(a[2]),"r"(a[3]),"r"(b0),"r"(b1));
}
__device__ __forceinline__ void cp16(uint32_t d, const void* s){
    asm volatile("cp.async.cg.shared.global [%0],[%1],16;"::"r"(d),"l"(s));
}
#define CP_COMMIT() asm volatile("cp.async.commit_group;":::"memory")
#define CP_WAIT(N)  asm volatile("cp.async.wait_group %0;"::"n"(N):"memory")
__device__ __forceinline__ void split2(float x, __nv_bfloat16& h, __nv_bfloat16& lo){
    h = __float2bfloat16(x); lo = __float2bfloat16(x - __bfloat162float(h));
}
// pack hi-planes / lo-planes of two floats into bf16x2 words
__device__ __forceinline__ void splitpair(float a, float b, uint32_t& hw, uint32_t& lw){
    __nv_bfloat16 ha, la, hb, lb;
    split2(a, ha, la); split2(b, hb, lb);
    hw = (uint32_t)__bfloat16_as_ushort(ha) | ((uint32_t)__bfloat16_as_ushort(hb) << 16);
    lw = (uint32_t)__bfloat16_as_ushort(la) | ((uint32_t)__bfloat16_as_ushort(lb) << 16);
}
__device__ __forceinline__ float fast_sigmoid(float x){
    float e; asm("ex2.approx.f32 %0,%1;":"=f"(e):"f"(-x*1.4426950408889634f));
    float r; asm("rcp.approx.f32 %0,%1;":"=f"(r):"f"(1.f+e));
    return r;
}

// ------------------- fused prep: KD | V | Q | PLOG -------------------
__global__ __launch_bounds__(256)
void prep_all(const float* __restrict__ q, const float* __restrict__ tk,
              const float* __restrict__ tv)
{
    const int bid = blockIdx.x, tid = threadIdx.x;
    const int lr = tid >> 6, k = tid & 63;

    if (bid < 16384){                       // ---- KD ----
        int gr = bid*4 + lr;
        int s = gr >> 8, r = gr & 255;
        float d = 0.f;
        if (r < 255){
            int rp = r+1, e = 31-__clz(rp), pj = rp-(1<<e);
            int j = e ? (int)(__brev((unsigned)pj) >> (32-e)) : 0;
            size_t node = (((size_t)1<<(e+8))-1) + (size_t)s*(1<<e) + j;
            d = tk[node*128 + k] - tk[node*128 + 64 + k];
        }
        __nv_bfloat16 h, lo; split2(d, h, lo);
        g_kdh[(size_t)gr*72 + k] = h; g_kdl[(size_t)gr*72 + k] = lo;
    } else if (bid < 32768){                // ---- V ----
        int gr = (bid - 16384)*4 + lr;
        int s = gr >> 8, r = gr & 255;
        size_t leaf = (size_t)s*256 + (__brev((unsigned)r) >> 24);
        float v = tv[leaf*64 + k];
        __nv_bfloat16 h, lo; split2(v, h, lo);
        g_vh[(size_t)gr*72 + k] = h; g_vl[(size_t)gr*72 + k] = lo;
    } else if (bid < 33280){                // ---- Q ----
        int b = (bid - 32768)*4 + lr;
        __nv_bfloat16 h, lo; split2(q[(size_t)b*64 + k], h, lo);
        g_qh[(size_t)b*72 + k] = h; g_ql[(size_t)b*72 + k] = lo;
    } else {                                // ---- PLOG ----
        extern __shared__ float ps[];
        float* qs = ps;                     // [k][b] stride 65
        float* ks = ps + 64*65;             // [j][k] 16 nodes
        int pb = bid - 33280;
        int btile = pb >> 4, slice = pb & 15;
        int b_base = btile * 64, n0 = slice * 16;
        for (int i = tid; i < 64*64; i += 256){
            int b = i >> 6, kk = i & 63;
            qs[kk*65 + b] = q[(size_t)(b_base + b)*64 + kk];
        }
        for (int i = tid; i < 16*64; i += 256){
            int j = i >> 6, kk = i & 63;
            int n = n0 + j;
            ks[i] = (n < 255) ? (tk[(size_t)n*128 + kk] - tk[(size_t)n*128 + 64 + kk]) : 0.f;
        }
        __syncthreads();
        int b = tid & 63, sub = tid >> 6;
        #pragma unroll
        for (int j2 = 0; j2 < 4; j2++){
            int j = sub*4 + j2, n = n0 + j;
            if (n >= 255) break;
            float acc = 0.f;
            #pragma unroll 16
            for (int kk = 0; kk < 64; kk++)
                acc = fmaf(qs[kk*65 + b], ks[j*64 + kk], acc);
            g_plog[(size_t)n*2048 + b_base + b] = acc;
        }
    }
}

// ----------------------------- main kernel -----------------------------
// T layout: slot-major float[257][72]. slot 0 = base prob (per batch word b);
// slot 1+node = sigma(logit(node)); expansion cum(pos) at slot pos.
// Level 7 packs split-bf16 leaf pairs in place (self-freed slots).
__global__ __launch_bounds__(256, 2)
void tree_kernel(float* __restrict__ out)
{
    extern __shared__ char smc[];
    float* fT = (float*)smc;
    uint32_t* uT = (uint32_t*)smc;
    float* fPB = (float*)(smc + SB_PB);
    const uint32_t SB = cvta(smc);
    const int tid = threadIdx.x, w = tid >> 5, l = tid & 31;
    const int btile = blockIdx.x, sg = blockIdx.y;
    const int b_base = btile * 64;
    const int bt = w & 3, grp = w >> 2;
    const int total = NS * 8;

    auto issue = [&](int t){
        if (t >= total) return;
        int c = t & 7, si = t >> 3;
        size_t off = ((size_t)(sg*NS + si)*256 + (size_t)(c & 3)*64)*72;
        const __nv_bfloat16 *ph = (c < 4) ? g_kdh + off : g_vh + off;
        const __nv_bfloat16 *pl = (c < 4) ? g_kdl + off : g_vl + off;
        uint32_t dst = SB + SB_BUF + (uint32_t)(t & 1)*18432;
        for (int i = tid; i < 576; i += 256){
            cp16(dst + i*16,        (const char*)ph + i*16);
            cp16(dst + 9216 + i*16, (const char*)pl + i*16);
        }
        CP_COMMIT();
    };

    issue(0); issue(1);

    // ---- Q fragments -> registers ----
    uint32_t QAh[4][4], QAl[4][4];
    {
        int r0 = b_base + bt*16 + (l >> 2);
        int c0 = 2 * (l & 3);
        #pragma unroll
        for (int kt = 0; kt < 4; kt++){
            int k0 = kt*16 + c0;
            QAh[kt][0] = *(const uint32_t*)&g_qh[(size_t)r0*72 + k0];
            QAh[kt][1] = *(const uint32_t*)&g_qh[(size_t)(r0+8)*72 + k0];
            QAh[kt][2] = *(const uint32_t*)&g_qh[(size_t)r0*72 + k0 + 8];
            QAh[kt][3] = *(const uint32_t*)&g_qh[(size_t)(r0+8)*72 + k0 + 8];
            QAl[kt][0] = *(const uint32_t*)&g_ql[(size_t)r0*72 + k0];
            QAl[kt][1] = *(const uint32_t*)&g_ql[(size_t)(r0+8)*72 + k0];
            QAl[kt][2] = *(const uint32_t*)&g_ql[(size_t)r0*72 + k0 + 8];
            QAl[kt][3] = *(const uint32_t*)&g_ql[(size_t)(r0+8)*72 + k0 + 8];
        }
    }

    // ---- 9 path logits per batch (coalesced; staged in T, dead before GEMM1) ----
    for (int i = tid; i < 9*64; i += 256){
        int n = i >> 6, b = i & 63;
        int node = (n < 7) ? ((1 << n) - 1 + (sg >> (6 - n)))
                           : (127 + 2*sg + (n - 7));
        fT[n*64 + b] = g_plog[(size_t)node*2048 + b_base + b];
    }
    __syncthreads();
    if (tid < 64){
        int b = tid;
        float common = 1.f;
        #pragma unroll
        for (int e = 0; e < 6; e++){
            int bit = (sg >> (5 - e)) & 1;
            float x = fT[e*64 + b];
            common *= fast_sigmoid(bit ? -x : x);
        }
        float s6  = fast_sigmoid(fT[6*64 + b]);
        float s7a = fast_sigmoid(fT[7*64 + b]);
        float s7b = fast_sigmoid(fT[8*64 + b]);
        fPB[0*64 + b] = common * s6 * s7a;
        fPB[1*64 + b] = common * s6 * (1.f - s7a);
        fPB[2*64 + b] = common * (1.f - s6) * s7b;
        fPB[3*64 + b] = common * (1.f - s6) * (1.f - s7b);
    }

    float acc2[4][4];
    #pragma unroll
    for (int i = 0; i < 4; i++)
        #pragma unroll
        for (int j = 0; j < 4; j++) acc2[i][j] = 0.f;

    for (int si = 0; si < NS; si++){
        // ---------------- GEMM1: 4 passes of 64 n-columns ----------------
        for (int p = 0; p < 4; p++){
            int t = si*8 + p;
            if (t + 1 < total) CP_WAIT(1); else CP_WAIT(0);
            __syncthreads();
            uint32_t kb = SB + SB_BUF + (uint32_t)(t & 1)*18432;
            float a1[4][4];
            #pragma unroll
            for (int i = 0; i < 4; i++)
                #pragma unroll
                for (int j = 0; j < 4; j++) a1[i][j] = 0.f;
            #pragma unroll
            for (int kt = 0; kt < 4; kt++){
                #pragma unroll
                for (int ntp = 0; ntp < 2; ntp++){
                    uint32_t bo = kb + (uint32_t)((
                        (grp*32 + ntp*16 + (((l >> 4) & 1) << 3) + (l & 7))*72
                        + kt*16 + (((l >> 3) & 1) << 3)) << 1);
                    uint32_t Bh[4], Bl[4];
                    ldsm4(Bh, bo); ldsm4(Bl, bo + 9216);
                    mma(a1[2*ntp],   QAh[kt], Bh[0], Bh[1]);
                    mma(a1[2*ntp],   QAh[kt], Bl[0], Bl[1]);
                    mma(a1[2*ntp],   QAl[kt], Bh[0], Bh[1]);
                    mma(a1[2*ntp+1], QAh[kt], Bh[2], Bh[3]);
                    mma(a1[2*ntp+1], QAh[kt], Bl[2], Bl[3]);
                    mma(a1[2*ntp+1], QAl[kt], Bh[2], Bh[3]);
                }
            }
            // sigma fused: store sigma(logit) into slot-major T [1+node][b]
            #pragma unroll
            for (int nt = 0; nt < 4; nt++){
                int r = bt*16 + (l >> 2);
                int cc = p*64 + grp*32 + nt*8 + 2*(l & 3);
                fT[(1 + cc)*72 + r]       = fast_sigmoid(a1[nt][0]);
                fT[(2 + cc)*72 + r]       = fast_sigmoid(a1[nt][1]);
                fT[(1 + cc)*72 + r + 8]   = fast_sigmoid(a1[nt][2]);
                fT[(2 + cc)*72 + r + 8]   = fast_sigmoid(a1[nt][3]);
            }
            __syncthreads();
            if (t + 2 < total) issue(t + 2);
        }
        if (tid < 64) fT[tid] = fPB[si*64 + tid];   // slot 0
        __syncthreads();

        // ------- expansion: slot-major, float2 batch pairs, conflict-free -------
        {
            const int wb = w * 8;
            #pragma unroll
            for (int e = 0; e < 7; e++){
                int half = 1 << e;
                for (int it = l; it < 4*half; it += 32){
                    int b2 = wb + 2*(it & 3), pos = it >> 2;
                    float2 sgv = *(float2*)&fT[(half + pos)*72 + b2];
                    float2 v   = *(float2*)&fT[pos*72 + b2];
                    float2 c0{ v.x * sgv.x, v.y * sgv.y };
                    float2 c1{ v.x - c0.x,  v.y - c0.y  };
                    *(float2*)&fT[pos*72 + b2]          = c0;
                    *(float2*)&fT[(pos + half)*72 + b2] = c1;
                }
                __syncwarp();
            }
            // level 7: pack split-bf16 leaf pairs into self-freed slots
            for (int it = l; it < 512; it += 32){
                int b = wb + (it & 7), pp = it >> 3;   // parent pair index 0..63
                float v0 = fT[(2*pp)*72 + b];
                float v1 = fT[(2*pp + 1)*72 + b];
                float s0 = fT[(128 + 2*pp)*72 + b];
                float s1 = fT[(128 + 2*pp + 1)*72 + b];
                float c0a = v0 * s0, c1a = v0 - c0a;   // leaves 2pp, 2pp+128
                float c0b = v1 * s1, c1b = v1 - c0b;   // leaves 2pp+1, 2pp+129
                uint32_t hw, lw;
                splitpair(c0a, c0b, hw, lw);           // leaf pair (2pp, 2pp+1)
                uT[(2*pp)*72 + b]           = hw;
                uT[(128 + 2*pp)*72 + b]     = lw;
                splitpair(c1a, c1b, hw, lw);           // leaf pair (128+2pp, 128+2pp+1)
                uT[(2*pp + 1)*72 + b]       = hw;
                uT[(128 + 2*pp + 1)*72 + b] = lw;
            }
        }
        __syncthreads();

        // ---------------- GEMM2: 4 k-chunks, register accumulator ----------------
        for (int c = 0; c < 4; c++){
            int t = si*8 + 4 + c;
            if (t + 1 < total) CP_WAIT(1); else CP_WAIT(0);
            __syncthreads();
            uint32_t vb = SB + SB_BUF + (uint32_t)(t & 1)*18432;
            #pragma unroll
            for (int kt = 0; kt < 4; kt++){
                int r0 = bt*16 + (l >> 2);
                // leaf-pair base P = c*32+kt*8; Ph slot = (P<64) ? 2P : 2P-127
                int Pb = c*32 + kt*8;
                int S  = (c < 2) ? 2*Pb : 2*Pb - 127;
                int sl = S + 2*(l & 3);
                uint32_t Ah[4], Al[4];
                Ah[0] = uT[sl*72 + r0];
                Ah[1] = uT[sl*72 + r0 + 8];
                Ah[2] = uT[(sl + 8)*72 + r0];
                Ah[3] = uT[(sl + 8)*72 + r0 + 8];
                Al[0] = uT[(sl + 128)*72 + r0];
                Al[1] = uT[(sl + 128)*72 + r0 + 8];
                Al[2] = uT[(sl + 136)*72 + r0];
                Al[3] = uT[(sl + 136)*72 + r0 + 8];
                #pragma unroll
                for (int dtp = 0; dtp < 2; dtp++){
                    uint32_t bo = vb + (uint32_t)((
                        (kt*16 + (((l >> 3) & 1) << 3) + (l & 7))*72
                        + grp*32 + dtp*16 + (((l >> 4) & 1) << 3)) << 1);
                    uint32_t Bh[4], Bl[4];
                    ldsm4t(Bh, bo); ldsm4t(Bl, bo + 9216);
                    mma(acc2[2*dtp],   Ah, Bh[0], Bh[1]);
                    mma(acc2[2*dtp],   Ah, Bl[0], Bl[1]);
                    mma(acc2[2*dtp],   Al, Bh[0], Bh[1]);
                    mma(acc2[2*dtp+1], Ah, Bh[2], Bh[3]);
                    mma(acc2[2*dtp+1], Ah, Bl[2], Bl[3]);
                    mma(acc2[2*dtp+1], Al, Bh[2], Bh[3]);
                }
            }
            __syncthreads();
            if (t + 2 < total) issue(t + 2);
        }
    }

    // ---------------- epilogue: one atomic pass per CTA ----------------
    #pragma unroll
    for (int dt = 0; dt < 4; dt++){
        int r = b_base + bt*16 + (l >> 2);
        int cc = grp*32 + dt*8 + 2*(l & 3);
        atomicAdd(&out[(size_t)r*64 + cc],         acc2[dt][0]);
        atomicAdd(&out[(size_t)r*64 + cc + 1],     acc2[dt][1]);
        atomicAdd(&out[(size_t)(r+8)*64 + cc],     acc2[dt][2]);
        atomicAdd(&out[(size_t)(r+8)*64 + cc + 1], acc2[dt][3]);
    }
}

extern "C" void kernel_launch(void* const* d_in, const int* in_sizes, int n_in,
                              void* d_out, int out_size) {
    const float* q  = (const float*)d_in[0];
    const float* tk = (const float*)d_in[1];
    const float* tv = (const float*)d_in[2];
    float* out = (float*)d_out;

    cudaFuncSetAttribute(tree_kernel,
                         cudaFuncAttributeMaxDynamicSharedMemorySize, SMEM_BYTES);

    cudaMemsetAsync(out, 0, (size_t)2048 * 64 * sizeof(float));
    prep_all<<<33792, 256, PLOG_SMEM>>>(q, tk, tv);
    tree_kernel<<<dim3(32, 64), 256, SMEM_BYTES>>>(out);
}

// round 13
// speedup vs baseline: 2.2363x; 1.0695x over previous
#include <cuda_runtime.h>
#include <cuda_bf16.h>
#include <cstdint>

#define NS 4
// smem (bytes): T = float[257 slots][72], 2 chunk bufs, base-prob scratch
#define SB_BUF  74016              // T = 257*72*4
#define SB_PB   110880             // float[4*64]
#define SMEM_BYTES 111904          // 2 CTAs/SM (<=113664)
#define PLOG_SMEM ((64*65 + 16*64) * 4)   // 20736

__device__ __align__(256) __nv_bfloat16 g_kdh[256*256*72];
__device__ __align__(256) __nv_bfloat16 g_kdl[256*256*72];
__device__ __align__(256) __nv_bfloat16 g_vh [256*256*72];
__device__ __align__(256) __nv_bfloat16 g_vl [256*256*72];
__device__ __align__(256) __nv_bfloat16 g_qh [2048*72];
__device__ __align__(256) __nv_bfloat16 g_ql [2048*72];
__device__ float g_plog[255*2048];  // fp32 logits, top-255 nodes

__device__ __forceinline__ uint32_t cvta(const void* p){
    uint32_t a; asm("{.reg .u64 t; cvta.to.shared.u64 t,%1; cvt.u32.u64 %0,t;}":"=r"(a):"l"(p)); return a;
}
__device__ __forceinline__ void ldsm4(uint32_t r[4], uint32_t a){
    asm volatile("ldmatrix.sync.aligned.m8n8.x4.shared.b16 {%0,%1,%2,%3},[%4];"
        :"=r"(r[0]),"=r"(r[1]),"=r"(r[2]),"=r"(r[3]):"r"(a));
}
__device__ __forceinline__ void ldsm4t(uint32_t r[4], uint32_t a){
    asm volatile("ldmatrix.sync.aligned.m8n8.x4.trans.shared.b16 {%0,%1,%2,%3},[%4];"
        :"=r"(r[0]),"=r"(r[1]),"=r"(r[2]),"=r"(r[3]):"r"(a));
}
__device__ __forceinline__ void mma(float c[4], const uint32_t a[4], const uint32_t b0, const uint32_t b1){
    asm volatile("mma.sync.aligned.m16n8k16.row.col.f32.bf16.bf16.f32 "
        "{%0,%1,%2,%3},{%4,%5,%6,%7},{%8,%9},{%0,%1,%2,%3};"
        :"+f"(c[0]),"+f"(c[1]),"+f"(c[2]),"+f"(c[3])
        :"r"(a[0]),"r"(a[1]),"r"(a[2]),"r"(a[3]),"r"(b0),"r"(b1));
}
__device__ __forceinline__ void cp16(uint32_t d, const void* s){
    asm volatile("cp.async.cg.shared.global [%0],[%1],16;"::"r"(d),"l"(s));
}
#define CP_COMMIT() asm volatile("cp.async.commit_group;":::"memory")
#define CP_WAIT(N)  asm volatile("cp.async.wait_group %0;"::"n"(N):"memory")
__device__ __forceinline__ void split2(float x, __nv_bfloat16& h, __nv_bfloat16& lo){
    h = __float2bfloat16(x); lo = __float2bfloat16(x - __bfloat162float(h));
}
// pack hi-planes / lo-planes of two floats into bf16x2 words
__device__ __forceinline__ void splitpair(float a, float b, uint32_t& hw, uint32_t& lw){
    __nv_bfloat16 ha, la, hb, lb;
    split2(a, ha, la); split2(b, hb, lb);
    hw = (uint32_t)__bfloat16_as_ushort(ha) | ((uint32_t)__bfloat16_as_ushort(hb) << 16);
    lw = (uint32_t)__bfloat16_as_ushort(la) | ((uint32_t)__bfloat16_as_ushort(lb) << 16);
}
__device__ __forceinline__ float fast_sigmoid(float x){
    float e; asm("ex2.approx.f32 %0,%1;":"=f"(e):"f"(-x*1.4426950408889634f));
    float r; asm("rcp.approx.f32 %0,%1;":"=f"(r):"f"(1.f+e));
    return r;
}
// hi-plane slot of leaf-pair P (bank-decorrelated, in-place-safe permutation)
__device__ __forceinline__ int slotH(int P){
    return (P < 64) ? (2*P + ((P >> 1) & 1))
                    : (2*(P - 64) + 1 - (((P - 64) >> 1) & 1));
}

// ------------------- fused prep: KD | V | Q | PLOG -------------------
__global__ __launch_bounds__(256)
void prep_all(const float* __restrict__ q, const float* __restrict__ tk,
              const float* __restrict__ tv)
{
    const int bid = blockIdx.x, tid = threadIdx.x;
    const int lr = tid >> 6, k = tid & 63;

    if (bid < 16384){                       // ---- KD ----
        int gr = bid*4 + lr;
        int s = gr >> 8, r = gr & 255;
        float d = 0.f;
        if (r < 255){
            int rp = r+1, e = 31-__clz(rp), pj = rp-(1<<e);
            int j = e ? (int)(__brev((unsigned)pj) >> (32-e)) : 0;
            size_t node = (((size_t)1<<(e+8))-1) + (size_t)s*(1<<e) + j;
            d = tk[node*128 + k] - tk[node*128 + 64 + k];
        }
        __nv_bfloat16 h, lo; split2(d, h, lo);
        g_kdh[(size_t)gr*72 + k] = h; g_kdl[(size_t)gr*72 + k] = lo;
    } else if (bid < 32768){                // ---- V ----
        int gr = (bid - 16384)*4 + lr;
        int s = gr >> 8, r = gr & 255;
        size_t leaf = (size_t)s*256 + (__brev((unsigned)r) >> 24);
        float v = tv[leaf*64 + k];
        __nv_bfloat16 h, lo; split2(v, h, lo);
        g_vh[(size_t)gr*72 + k] = h; g_vl[(size_t)gr*72 + k] = lo;
    } else if (bid < 33280){                // ---- Q ----
        int b = (bid - 32768)*4 + lr;
        __nv_bfloat16 h, lo; split2(q[(size_t)b*64 + k], h, lo);
        g_qh[(size_t)b*72 + k] = h; g_ql[(size_t)b*72 + k] = lo;
    } else {                                // ---- PLOG ----
        extern __shared__ float ps[];
        float* qs = ps;                     // [k][b] stride 65
        float* ks = ps + 64*65;             // [j][k] 16 nodes
        int pb = bid - 33280;
        int btile = pb >> 4, slice = pb & 15;
        int b_base = btile * 64, n0 = slice * 16;
        for (int i = tid; i < 64*64; i += 256){
            int b = i >> 6, kk = i & 63;
            qs[kk*65 + b] = q[(size_t)(b_base + b)*64 + kk];
        }
        for (int i = tid; i < 16*64; i += 256){
            int j = i >> 6, kk = i & 63;
            int n = n0 + j;
            ks[i] = (n < 255) ? (tk[(size_t)n*128 + kk] - tk[(size_t)n*128 + 64 + kk]) : 0.f;
        }
        __syncthreads();
        int b = tid & 63, sub = tid >> 6;
        #pragma unroll
        for (int j2 = 0; j2 < 4; j2++){
            int j = sub*4 + j2, n = n0 + j;
            if (n >= 255) break;
            float acc = 0.f;
            #pragma unroll 16
            for (int kk = 0; kk < 64; kk++)
                acc = fmaf(qs[kk*65 + b], ks[j*64 + kk], acc);
            g_plog[(size_t)n*2048 + b_base + b] = acc;
        }
    }
}

// ----------------------------- main kernel -----------------------------
// T: slot-major float[257][72]. slot 0 = base prob; slot 2^e+pos = sigma of
// expansion level e; cum(pos) at slot pos. Level 7 packs split-bf16 leaf
// pairs in place with a bank-decorrelating permutation (slotH).
__global__ __launch_bounds__(256, 2)
void tree_kernel(float* __restrict__ out)
{
    extern __shared__ char smc[];
    float* fT = (float*)smc;
    uint32_t* uT = (uint32_t*)smc;
    float* fPB = (float*)(smc + SB_PB);
    const uint32_t SB = cvta(smc);
    const int tid = threadIdx.x, w = tid >> 5, l = tid & 31;
    const int btile = blockIdx.x, sg = blockIdx.y;
    const int b_base = btile * 64;
    const int bt = w & 3, grp = w >> 2;
    const int total = NS * 8;

    auto issue = [&](int t){
        if (t >= total) return;
        int c = t & 7, si = t >> 3;
        size_t off = ((size_t)(sg*NS + si)*256 + (size_t)(c & 3)*64)*72;
        const __nv_bfloat16 *ph = (c < 4) ? g_kdh + off : g_vh + off;
        const __nv_bfloat16 *pl = (c < 4) ? g_kdl + off : g_vl + off;
        uint32_t dst = SB + SB_BUF + (uint32_t)(t & 1)*18432;
        for (int i = tid; i < 576; i += 256){
            cp16(dst + i*16,        (const char*)ph + i*16);
            cp16(dst + 9216 + i*16, (const char*)pl + i*16);
        }
        CP_COMMIT();
    };

    issue(0); issue(1);

    // ---- Q fragments -> registers ----
    uint32_t QAh[4][4], QAl[4][4];
    {
        int r0 = b_base + bt*16 + (l >> 2);
        int c0 = 2 * (l & 3);
        #pragma unroll
        for (int kt = 0; kt < 4; kt++){
            int k0 = kt*16 + c0;
            QAh[kt][0] = *(const uint32_t*)&g_qh[(size_t)r0*72 + k0];
            QAh[kt][1] = *(const uint32_t*)&g_qh[(size_t)(r0+8)*72 + k0];
            QAh[kt][2] = *(const uint32_t*)&g_qh[(size_t)r0*72 + k0 + 8];
            QAh[kt][3] = *(const uint32_t*)&g_qh[(size_t)(r0+8)*72 + k0 + 8];
            QAl[kt][0] = *(const uint32_t*)&g_ql[(size_t)r0*72 + k0];
            QAl[kt][1] = *(const uint32_t*)&g_ql[(size_t)(r0+8)*72 + k0];
            QAl[kt][2] = *(const uint32_t*)&g_ql[(size_t)r0*72 + k0 + 8];
            QAl[kt][3] = *(const uint32_t*)&g_ql[(size_t)(r0+8)*72 + k0 + 8];
        }
    }

    // ---- 9 path logits per batch (coalesced; staged in T, dead before GEMM1) ----
    for (int i = tid; i < 9*64; i += 256){
        int n = i >> 6, b = i & 63;
        int node = (n < 7) ? ((1 << n) - 1 + (sg >> (6 - n)))
                           : (127 + 2*sg + (n - 7));
        fT[n*64 + b] = g_plog[(size_t)node*2048 + b_base + b];
    }
    __syncthreads();
    if (tid < 64){
        int b = tid;
        float common = 1.f;
        #pragma unroll
        for (int e = 0; e < 6; e++){
            int bit = (sg >> (5 - e)) & 1;
            float x = fT[e*64 + b];
            common *= fast_sigmoid(bit ? -x : x);
        }
        float s6  = fast_sigmoid(fT[6*64 + b]);
        float s7a = fast_sigmoid(fT[7*64 + b]);
        float s7b = fast_sigmoid(fT[8*64 + b]);
        fPB[0*64 + b] = common * s6 * s7a;
        fPB[1*64 + b] = common * s6 * (1.f - s7a);
        fPB[2*64 + b] = common * (1.f - s6) * s7b;
        fPB[3*64 + b] = common * (1.f - s6) * (1.f - s7b);
    }

    float acc2[4][4];
    #pragma unroll
    for (int i = 0; i < 4; i++)
        #pragma unroll
        for (int j = 0; j < 4; j++) acc2[i][j] = 0.f;

    for (int si = 0; si < NS; si++){
        // ---------------- GEMM1: 4 passes of 64 n-columns ----------------
        for (int p = 0; p < 4; p++){
            int t = si*8 + p;
            if (t + 1 < total) CP_WAIT(1); else CP_WAIT(0);
            __syncthreads();
            uint32_t kb = SB + SB_BUF + (uint32_t)(t & 1)*18432;
            float a1[4][4];
            #pragma unroll
            for (int i = 0; i < 4; i++)
                #pragma unroll
                for (int j = 0; j < 4; j++) a1[i][j] = 0.f;
            #pragma unroll
            for (int kt = 0; kt < 4; kt++){
                #pragma unroll
                for (int ntp = 0; ntp < 2; ntp++){
                    uint32_t bo = kb + (uint32_t)((
                        (grp*32 + ntp*16 + (((l >> 4) & 1) << 3) + (l & 7))*72
                        + kt*16 + (((l >> 3) & 1) << 3)) << 1);
                    uint32_t Bh[4], Bl[4];
                    ldsm4(Bh, bo); ldsm4(Bl, bo + 9216);
                    mma(a1[2*ntp],   QAh[kt], Bh[0], Bh[1]);
                    mma(a1[2*ntp],   QAh[kt], Bl[0], Bl[1]);
                    mma(a1[2*ntp],   QAl[kt], Bh[0], Bh[1]);
                    mma(a1[2*ntp+1], QAh[kt], Bh[2], Bh[3]);
                    mma(a1[2*ntp+1], QAh[kt], Bl[2], Bl[3]);
                    mma(a1[2*ntp+1], QAl[kt], Bh[2], Bh[3]);
                }
            }
            // sigma fused: store sigma(logit) into slot-major T [1+node][b]
            #pragma unroll
            for (int nt = 0; nt < 4; nt++){
                int r = bt*16 + (l >> 2);
                int cc = p*64 + grp*32 + nt*8 + 2*(l & 3);
                fT[(1 + cc)*72 + r]       = fast_sigmoid(a1[nt][0]);
                fT[(2 + cc)*72 + r]       = fast_sigmoid(a1[nt][1]);
                fT[(1 + cc)*72 + r + 8]   = fast_sigmoid(a1[nt][2]);
                fT[(2 + cc)*72 + r + 8]   = fast_sigmoid(a1[nt][3]);
            }
            __syncthreads();
            if (t + 2 < total) issue(t + 2);
        }
        if (tid < 64) fT[tid] = fPB[si*64 + tid];   // slot 0
        __syncthreads();

        // ------- expansion: fused triple levels, in-place, conflict-light -------
        {
            const int wb = w * 8;
            // step A: levels 0,1,2 (1 parent -> 8) ; lanes 0-3 per warp
            if (l < 4){
                int b2 = wb + 2*l;
                float2 v   = *(float2*)&fT[0*72 + b2];
                float2 s0  = *(float2*)&fT[1*72 + b2];
                float2 s10 = *(float2*)&fT[2*72 + b2];
                float2 s11 = *(float2*)&fT[3*72 + b2];
                float2 s2[4];
                #pragma unroll
                for (int j = 0; j < 4; j++) s2[j] = *(float2*)&fT[(4+j)*72 + b2];
                float2 a0{v.x*s0.x, v.y*s0.y}, a1v{v.x-a0.x, v.y-a0.y};
                float2 bb[4];
                bb[0] = {a0.x*s10.x,  a0.y*s10.y};  bb[2] = {a0.x-bb[0].x,  a0.y-bb[0].y};
                bb[1] = {a1v.x*s11.x, a1v.y*s11.y}; bb[3] = {a1v.x-bb[1].x, a1v.y-bb[1].y};
                #pragma unroll
                for (int j = 0; j < 4; j++){
                    float2 c0{bb[j].x*s2[j].x, bb[j].y*s2[j].y};
                    float2 c1{bb[j].x-c0.x,    bb[j].y-c0.y};
                    *(float2*)&fT[j*72 + b2]     = c0;
                    *(float2*)&fT[(j+4)*72 + b2] = c1;
                }
            }
            __syncwarp();
            // step B: levels 3,4,5 (8 parents -> 64); exactly 32 lanes
            {
                int pos = l >> 2, b2 = wb + 2*(l & 3);
                float2 v   = *(float2*)&fT[pos*72 + b2];
                float2 s3  = *(float2*)&fT[(8+pos)*72 + b2];
                float2 s40 = *(float2*)&fT[(16+pos)*72 + b2];
                float2 s41 = *(float2*)&fT[(24+pos)*72 + b2];
                float2 s5[4];
                #pragma unroll
                for (int j = 0; j < 4; j++) s5[j] = *(float2*)&fT[(32+8*j+pos)*72 + b2];
                float2 a0{v.x*s3.x, v.y*s3.y}, a1v{v.x-a0.x, v.y-a0.y};
                float2 bb[4];
                bb[0] = {a0.x*s40.x,  a0.y*s40.y};  bb[2] = {a0.x-bb[0].x,  a0.y-bb[0].y};
                bb[1] = {a1v.x*s41.x, a1v.y*s41.y}; bb[3] = {a1v.x-bb[1].x, a1v.y-bb[1].y};
                #pragma unroll
                for (int j = 0; j < 4; j++){
                    float2 c0{bb[j].x*s5[j].x, bb[j].y*s5[j].y};
                    float2 c1{bb[j].x-c0.x,    bb[j].y-c0.y};
                    *(float2*)&fT[(8*j+pos)*72 + b2]      = c0;
                    *(float2*)&fT[(32+8*j+pos)*72 + b2]   = c1;
                }
            }
            __syncwarp();
            // level 6 (64 parents -> 128)
            for (int it = l; it < 256; it += 32){
                int pos = it >> 2, b2 = wb + 2*(it & 3);
                float2 v = *(float2*)&fT[pos*72 + b2];
                float2 s = *(float2*)&fT[(64+pos)*72 + b2];
                float2 c0{v.x*s.x, v.y*s.y};
                float2 c1{v.x-c0.x, v.y-c0.y};
                *(float2*)&fT[pos*72 + b2]      = c0;
                *(float2*)&fT[(64+pos)*72 + b2] = c1;
            }
            __syncwarp();
            // level 7 + split-pack (permuted slots), float2 batch pairs
            for (int it = l; it < 256; it += 32){
                int pp = it >> 2, b2 = wb + 2*(it & 3);
                float2 v0 = *(float2*)&fT[(2*pp)*72 + b2];
                float2 v1 = *(float2*)&fT[(2*pp+1)*72 + b2];
                float2 s0 = *(float2*)&fT[(128+2*pp)*72 + b2];
                float2 s1 = *(float2*)&fT[(129+2*pp)*72 + b2];
                float c0ax = v0.x*s0.x, c1ax = v0.x-c0ax;
                float c0bx = v1.x*s1.x, c1bx = v1.x-c0bx;
                float c0ay = v0.y*s0.y, c1ay = v0.y-c0ay;
                float c0by = v1.y*s1.y, c1by = v1.y-c0by;
                uint32_t h1x,l1x,h2x,l2x,h1y,l1y,h2y,l2y;
                splitpair(c0ax, c0bx, h1x, l1x);
                splitpair(c1ax, c1bx, h2x, l2x);
                splitpair(c0ay, c0by, h1y, l1y);
                splitpair(c1ay, c1by, h2y, l2y);
                int tt = (pp >> 1) & 1;
                int s1h = 2*pp + tt, s2h = 2*pp + 1 - tt;
                *(uint2*)&uT[s1h*72 + b2]         = make_uint2(h1x, h1y);
                *(uint2*)&uT[s2h*72 + b2]         = make_uint2(h2x, h2y);
                *(uint2*)&uT[(s1h+128)*72 + b2]   = make_uint2(l1x, l1y);
                *(uint2*)&uT[(s2h+128)*72 + b2]   = make_uint2(l2x, l2y);
            }
        }
        __syncthreads();

        // ---------------- GEMM2: 4 k-chunks, register accumulator ----------------
        for (int c = 0; c < 4; c++){
            int t = si*8 + 4 + c;
            if (t + 1 < total) CP_WAIT(1); else CP_WAIT(0);
            __syncthreads();
            uint32_t vb = SB + SB_BUF + (uint32_t)(t & 1)*18432;
            #pragma unroll
            for (int kt = 0; kt < 4; kt++){
                int r0 = bt*16 + (l >> 2);
                int Pb = c*32 + kt*8;
                int Pa = Pb + (l & 3), Pc = Pb + 4 + (l & 3);
                int sa = slotH(Pa), sc = slotH(Pc);
                uint32_t Ah[4], Al[4];
                Ah[0] = uT[sa*72 + r0];
                Ah[1] = uT[sa*72 + r0 + 8];
                Ah[2] = uT[sc*72 + r0];
                Ah[3] = uT[sc*72 + r0 + 8];
                Al[0] = uT[(sa+128)*72 + r0];
                Al[1] = uT[(sa+128)*72 + r0 + 8];
                Al[2] = uT[(sc+128)*72 + r0];
                Al[3] = uT[(sc+128)*72 + r0 + 8];
                #pragma unroll
                for (int dtp = 0; dtp < 2; dtp++){
                    uint32_t bo = vb + (uint32_t)((
                        (kt*16 + (((l >> 3) & 1) << 3) + (l & 7))*72
                        + grp*32 + dtp*16 + (((l >> 4) & 1) << 3)) << 1);
                    uint32_t Bh[4], Bl[4];
                    ldsm4t(Bh, bo); ldsm4t(Bl, bo + 9216);
                    mma(acc2[2*dtp],   Ah, Bh[0], Bh[1]);
                    mma(acc2[2*dtp],   Ah, Bl[0], Bl[1]);
                    mma(acc2[2*dtp],   Al, Bh[0], Bh[1]);
                    mma(acc2[2*dtp+1], Ah, Bh[2], Bh[3]);
                    mma(acc2[2*dtp+1], Ah, Bl[2], Bl[3]);
                    mma(acc2[2*dtp+1], Al, Bh[2], Bh[3]);
                }
            }
            __syncthreads();
            if (t + 2 < total) issue(t + 2);
        }
    }

    // ---------------- epilogue: one atomic pass per CTA ----------------
    #pragma unroll
    for (int dt = 0; dt < 4; dt++){
        int r = b_base + bt*16 + (l >> 2);
        int cc = grp*32 + dt*8 + 2*(l & 3);
        atomicAdd(&out[(size_t)r*64 + cc],         acc2[dt][0]);
        atomicAdd(&out[(size_t)r*64 + cc + 1],     acc2[dt][1]);
        atomicAdd(&out[(size_t)(r+8)*64 + cc],     acc2[dt][2]);
        atomicAdd(&out[(size_t)(r+8)*64 + cc + 1], acc2[dt][3]);
    }
}

extern "C" void kernel_launch(void* const* d_in, const int* in_sizes, int n_in,
                              void* d_out, int out_size) {
    const float* q  = (const float*)d_in[0];
    const float* tk = (const float*)d_in[1];
    const float* tv = (const float*)d_in[2];
    float* out = (float*)d_out;

    cudaFuncSetAttribute(tree_kernel,
                         cudaFuncAttributeMaxDynamicSharedMemorySize, SMEM_BYTES);

    cudaMemsetAsync(out, 0, (size_t)2048 * 64 * sizeof(float));
    prep_all<<<33792, 256, PLOG_SMEM>>>(q, tk, tv);
    tree_kernel<<<dim3(32, 64), 256, SMEM_BYTES>>>(out);
}